// round 3
// baseline (speedup 1.0000x reference)
#include <cuda_runtime.h>

// ---------------------------------------------------------------------------
// MultiHeadAttention: out = LN( softmax(QK^T/sqrt(d)) V @ Wo + bo ) + query
// B=4, N=2048, DIM=1024, HEADS=16, DH=64
// Round-2 baseline: fp32 SIMT tiled GEMMs + flash attention + fused LN.
// ---------------------------------------------------------------------------

#define BC    4
#define NSEQ  2048
#define DIMC  1024
#define HEADS 16
#define DHEAD 64
#define MTOT  (BC * NSEQ)   // 8192

// Scratch (device globals: allocation-free per harness rules)
__device__ float g_q[MTOT * DIMC];     // [B,H,N,DH]
__device__ float g_k[MTOT * DIMC];     // [B,H,N,DH]
__device__ float g_v[MTOT * DIMC];     // [B,H,N,DH]
__device__ float g_attn[MTOT * DIMC];  // [B,N,H*DH]
__device__ float g_proj[MTOT * DIMC];  // attn @ Wo + bo

// ---------------------------------------------------------------------------
// GEMM 1: fused QKV projection. C = X @ W, written in [B,H,N,DH] layout.
// 128x128 tile, BK=8, 256 threads, 8x8 per thread.
// ---------------------------------------------------------------------------
__global__ __launch_bounds__(256) void sgemm_qkv(
    const float* __restrict__ Xq, const float* __restrict__ Xk,
    const float* __restrict__ Xv, const float* __restrict__ Wq,
    const float* __restrict__ Wk, const float* __restrict__ Wv)
{
    const float* A;
    const float* W;
    float* C;
    if (blockIdx.z == 0)      { A = Xq; W = Wq; C = g_q; }
    else if (blockIdx.z == 1) { A = Xk; W = Wk; C = g_k; }
    else                      { A = Xv; W = Wv; C = g_v; }

    __shared__ float As[8][128];   // [kk][row]  (A transposed)
    __shared__ float Bs[8][128];   // [kk][col]

    const int tid = threadIdx.x;
    const int bm = blockIdx.x * 128;
    const int bn = blockIdx.y * 128;

    const int tm = (tid >> 4) * 8;
    const int tn = (tid & 15) * 8;

    // A loader: 1 float4 / thread, transposed into As
    const int arow = tid >> 1;
    const int akq  = (tid & 1) * 4;
    // B loader: 1 float4 / thread
    const int brow = tid >> 5;
    const int bcol = (tid & 31) * 4;

    float acc[8][8];
#pragma unroll
    for (int i = 0; i < 8; i++)
#pragma unroll
        for (int j = 0; j < 8; j++) acc[i][j] = 0.f;

    for (int k0 = 0; k0 < DIMC; k0 += 8) {
        float4 av = *(const float4*)(A + (bm + arow) * DIMC + k0 + akq);
        float4 bv = *(const float4*)(W + (k0 + brow) * DIMC + bn + bcol);
        As[akq + 0][arow] = av.x;
        As[akq + 1][arow] = av.y;
        As[akq + 2][arow] = av.z;
        As[akq + 3][arow] = av.w;
        *(float4*)&Bs[brow][bcol] = bv;
        __syncthreads();

#pragma unroll
        for (int kk = 0; kk < 8; kk++) {
            float4 a0 = *(float4*)&As[kk][tm];
            float4 a1 = *(float4*)&As[kk][tm + 4];
            float4 b0 = *(float4*)&Bs[kk][tn];
            float4 b1 = *(float4*)&Bs[kk][tn + 4];
            float a[8] = {a0.x, a0.y, a0.z, a0.w, a1.x, a1.y, a1.z, a1.w};
            float b[8] = {b0.x, b0.y, b0.z, b0.w, b1.x, b1.y, b1.z, b1.w};
#pragma unroll
            for (int i = 0; i < 8; i++)
#pragma unroll
                for (int j = 0; j < 8; j++) acc[i][j] += a[i] * b[j];
        }
        __syncthreads();
    }

    // Epilogue: scatter into [B,H,N,DH]. Cols are head-aligned (tn % 8 == 0).
#pragma unroll
    for (int i = 0; i < 8; i++) {
        int row = bm + tm + i;
        int b = row >> 11;       // / NSEQ
        int n = row & 2047;      // % NSEQ
#pragma unroll
        for (int j4 = 0; j4 < 8; j4 += 4) {
            int col = bn + tn + j4;
            int h = col >> 6;
            int d = col & 63;
            float4 v = make_float4(acc[i][j4], acc[i][j4 + 1],
                                   acc[i][j4 + 2], acc[i][j4 + 3]);
            *(float4*)&C[(((b * HEADS + h) * NSEQ) + n) * DHEAD + d] = v;
        }
    }
}

// ---------------------------------------------------------------------------
// GEMM 2: g_proj = g_attn @ Wo + bo   (plain [M, DIM] layout)
// ---------------------------------------------------------------------------
__global__ __launch_bounds__(256) void sgemm_wo(
    const float* __restrict__ Wo, const float* __restrict__ bo)
{
    const float* A = g_attn;
    __shared__ float As[8][128];
    __shared__ float Bs[8][128];

    const int tid = threadIdx.x;
    const int bm = blockIdx.x * 128;
    const int bn = blockIdx.y * 128;
    const int tm = (tid >> 4) * 8;
    const int tn = (tid & 15) * 8;
    const int arow = tid >> 1;
    const int akq  = (tid & 1) * 4;
    const int brow = tid >> 5;
    const int bcol = (tid & 31) * 4;

    float acc[8][8];
#pragma unroll
    for (int i = 0; i < 8; i++)
#pragma unroll
        for (int j = 0; j < 8; j++) acc[i][j] = 0.f;

    for (int k0 = 0; k0 < DIMC; k0 += 8) {
        float4 av = *(const float4*)(A + (bm + arow) * DIMC + k0 + akq);
        float4 bv = *(const float4*)(Wo + (k0 + brow) * DIMC + bn + bcol);
        As[akq + 0][arow] = av.x;
        As[akq + 1][arow] = av.y;
        As[akq + 2][arow] = av.z;
        As[akq + 3][arow] = av.w;
        *(float4*)&Bs[brow][bcol] = bv;
        __syncthreads();

#pragma unroll
        for (int kk = 0; kk < 8; kk++) {
            float4 a0 = *(float4*)&As[kk][tm];
            float4 a1 = *(float4*)&As[kk][tm + 4];
            float4 b0 = *(float4*)&Bs[kk][tn];
            float4 b1 = *(float4*)&Bs[kk][tn + 4];
            float a[8] = {a0.x, a0.y, a0.z, a0.w, a1.x, a1.y, a1.z, a1.w};
            float b[8] = {b0.x, b0.y, b0.z, b0.w, b1.x, b1.y, b1.z, b1.w};
#pragma unroll
            for (int i = 0; i < 8; i++)
#pragma unroll
                for (int j = 0; j < 8; j++) acc[i][j] += a[i] * b[j];
        }
        __syncthreads();
    }

#pragma unroll
    for (int i = 0; i < 8; i++) {
        int row = bm + tm + i;
#pragma unroll
        for (int j4 = 0; j4 < 8; j4 += 4) {
            int col = bn + tn + j4;
            float4 bb = *(const float4*)&bo[col];
            float4 v = make_float4(acc[i][j4] + bb.x, acc[i][j4 + 1] + bb.y,
                                   acc[i][j4 + 2] + bb.z, acc[i][j4 + 3] + bb.w);
            *(float4*)&g_proj[row * DIMC + col] = v;
        }
    }
}

// ---------------------------------------------------------------------------
// Flash attention, fp32. Grid: (N/64, B*H). 256 threads.
// Per block: 64 query rows of one (b,h); loop over 32 KV tiles of 64 rows.
// smem: sQT/sKT/sV/sPT, each [64][68] fp32 = 69,632 B dynamic.
// ---------------------------------------------------------------------------
#define ATTN_SMEM (4 * 64 * 68 * 4)

__global__ __launch_bounds__(256) void attn_kernel()
{
    extern __shared__ float sm[];
    float (*sQT)[68] = (float(*)[68])(sm);               // [kk][qrow], pre-scaled
    float (*sKT)[68] = (float(*)[68])(sm + 64 * 68);     // [kk][krow]
    float (*sV)[68]  = (float(*)[68])(sm + 2 * 64 * 68); // [krow][d]
    float (*sPT)[68] = (float(*)[68])(sm + 3 * 64 * 68); // [krow][qrow]

    const int tid = threadIdx.x;
    const int qt = blockIdx.x;            // query tile
    const int bh = blockIdx.y;            // b*HEADS + h
    const float* Qg = g_q + bh * NSEQ * DHEAD + qt * 64 * DHEAD;
    const float* Kg = g_k + bh * NSEQ * DHEAD;
    const float* Vg = g_v + bh * NSEQ * DHEAD;

    const float scale = 0.125f;           // 1/sqrt(64)

    // Load Q tile transposed + pre-scaled
#pragma unroll
    for (int c = 0; c < 4; c++) {
        int flat = c * 256 + tid;
        int row = flat >> 4;
        int col = (flat & 15) * 4;
        float4 v = *(const float4*)(Qg + row * DHEAD + col);
        sQT[col + 0][row] = v.x * scale;
        sQT[col + 1][row] = v.y * scale;
        sQT[col + 2][row] = v.z * scale;
        sQT[col + 3][row] = v.w * scale;
    }

    const int r0 = (tid >> 4) * 4;   // query rows of this thread
    const int c0 = (tid & 15) * 4;   // key cols (GEMM1) / out dims (GEMM2)

    float mrow[4], lrow[4], o[4][4];
#pragma unroll
    for (int i = 0; i < 4; i++) {
        mrow[i] = -1e30f;
        lrow[i] = 0.f;
#pragma unroll
        for (int j = 0; j < 4; j++) o[i][j] = 0.f;
    }

    for (int kt = 0; kt < NSEQ / 64; kt++) {
        __syncthreads();   // previous GEMM2 done with sV/sPT, GEMM1 with sKT
        // Load K (transposed) and V (row-major) tiles
#pragma unroll
        for (int c = 0; c < 4; c++) {
            int flat = c * 256 + tid;
            int row = flat >> 4;
            int col = (flat & 15) * 4;
            float4 kv = *(const float4*)(Kg + kt * 64 * DHEAD + row * DHEAD + col);
            sKT[col + 0][row] = kv.x;
            sKT[col + 1][row] = kv.y;
            sKT[col + 2][row] = kv.z;
            sKT[col + 3][row] = kv.w;
            float4 vv = *(const float4*)(Vg + kt * 64 * DHEAD + row * DHEAD + col);
            *(float4*)&sV[row][col] = vv;
        }
        __syncthreads();

        // GEMM1: s = (Q*scale) @ K^T  (64x64), thread owns 4x4
        float s[4][4];
#pragma unroll
        for (int i = 0; i < 4; i++)
#pragma unroll
            for (int j = 0; j < 4; j++) s[i][j] = 0.f;

#pragma unroll 16
        for (int kk = 0; kk < 64; kk++) {
            float4 aq = *(float4*)&sQT[kk][r0];
            float4 bk = *(float4*)&sKT[kk][c0];
            float a[4] = {aq.x, aq.y, aq.z, aq.w};
            float b[4] = {bk.x, bk.y, bk.z, bk.w};
#pragma unroll
            for (int i = 0; i < 4; i++)
#pragma unroll
                for (int j = 0; j < 4; j++) s[i][j] += a[i] * b[j];
        }

        // Online softmax; row group = 16 consecutive lanes (same tid>>4)
#pragma unroll
        for (int i = 0; i < 4; i++) {
            float mt = fmaxf(fmaxf(s[i][0], s[i][1]), fmaxf(s[i][2], s[i][3]));
            mt = fmaxf(mt, __shfl_xor_sync(0xffffffffu, mt, 1));
            mt = fmaxf(mt, __shfl_xor_sync(0xffffffffu, mt, 2));
            mt = fmaxf(mt, __shfl_xor_sync(0xffffffffu, mt, 4));
            mt = fmaxf(mt, __shfl_xor_sync(0xffffffffu, mt, 8));
            float mnew = fmaxf(mrow[i], mt);
            float corr = __expf(mrow[i] - mnew);
            float rs = 0.f;
#pragma unroll
            for (int j = 0; j < 4; j++) {
                float p = __expf(s[i][j] - mnew);
                sPT[c0 + j][r0 + i] = p;
                rs += p;
            }
            rs += __shfl_xor_sync(0xffffffffu, rs, 1);
            rs += __shfl_xor_sync(0xffffffffu, rs, 2);
            rs += __shfl_xor_sync(0xffffffffu, rs, 4);
            rs += __shfl_xor_sync(0xffffffffu, rs, 8);
            lrow[i] = lrow[i] * corr + rs;
            mrow[i] = mnew;
#pragma unroll
            for (int j = 0; j < 4; j++) o[i][j] *= corr;
        }
        __syncthreads();   // sPT visible to all

        // GEMM2: o += P @ V   (thread: rows r0.., out dims c0..)
#pragma unroll 16
        for (int j2 = 0; j2 < 64; j2++) {
            float4 ap = *(float4*)&sPT[j2][r0];
            float4 bv = *(float4*)&sV[j2][c0];
            float a[4] = {ap.x, ap.y, ap.z, ap.w};
            float b[4] = {bv.x, bv.y, bv.z, bv.w};
#pragma unroll
            for (int i = 0; i < 4; i++)
#pragma unroll
                for (int j = 0; j < 4; j++) o[i][j] += a[i] * b[j];
        }
    }

    // Write [B,N,H*DH]
    const int b = bh >> 4;
    const int h = bh & 15;
#pragma unroll
    for (int i = 0; i < 4; i++) {
        float inv = 1.0f / lrow[i];
        int n = qt * 64 + r0 + i;
        float4 v = make_float4(o[i][0] * inv, o[i][1] * inv,
                               o[i][2] * inv, o[i][3] * inv);
        *(float4*)&g_attn[(b * NSEQ + n) * DIMC + h * DHEAD + c0] = v;
    }
}

// ---------------------------------------------------------------------------
// LayerNorm over last dim + residual. One block per row.
// ---------------------------------------------------------------------------
__global__ __launch_bounds__(256) void ln_kernel(
    const float* __restrict__ query, const float* __restrict__ gamma,
    const float* __restrict__ beta, float* __restrict__ out)
{
    const int r = blockIdx.x;
    const float* x = g_proj + (size_t)r * DIMC;

    float v[4];
    float s = 0.f, ss = 0.f;
#pragma unroll
    for (int i = 0; i < 4; i++) {
        v[i] = x[threadIdx.x + 256 * i];
        s += v[i];
        ss += v[i] * v[i];
    }
#pragma unroll
    for (int ofs = 16; ofs > 0; ofs >>= 1) {
        s  += __shfl_xor_sync(0xffffffffu, s,  ofs);
        ss += __shfl_xor_sync(0xffffffffu, ss, ofs);
    }
    __shared__ float rs[8], rss[8];
    int w = threadIdx.x >> 5, lane = threadIdx.x & 31;
    if (lane == 0) { rs[w] = s; rss[w] = ss; }
    __syncthreads();
    if (threadIdx.x == 0) {
        float a = 0.f, b2 = 0.f;
#pragma unroll
        for (int i = 0; i < 8; i++) { a += rs[i]; b2 += rss[i]; }
        rs[0] = a; rss[0] = b2;
    }
    __syncthreads();
    const float mean = rs[0] * (1.0f / DIMC);
    const float var  = rss[0] * (1.0f / DIMC) - mean * mean;
    const float inv  = rsqrtf(var + 1e-5f);

#pragma unroll
    for (int i = 0; i < 4; i++) {
        int c = threadIdx.x + 256 * i;
        size_t idx = (size_t)r * DIMC + c;
        out[idx] = (v[i] - mean) * inv * gamma[c] + beta[c] + query[idx];
    }
}

// ---------------------------------------------------------------------------
extern "C" void kernel_launch(void* const* d_in, const int* in_sizes, int n_in,
                              void* d_out, int out_size)
{
    const float* query = (const float*)d_in[0];
    const float* key_  = (const float*)d_in[1];
    const float* value = (const float*)d_in[2];
    const float* Wq    = (const float*)d_in[3];
    const float* Wk    = (const float*)d_in[4];
    const float* Wv    = (const float*)d_in[5];
    const float* Wo    = (const float*)d_in[6];
    const float* bo    = (const float*)d_in[7];
    const float* gamma = (const float*)d_in[8];
    const float* beta  = (const float*)d_in[9];
    float* out = (float*)d_out;

    // Idempotent; safe during graph capture (not a stream op).
    cudaFuncSetAttribute(attn_kernel,
                         cudaFuncAttributeMaxDynamicSharedMemorySize, ATTN_SMEM);

    // 1) QKV projections -> [B,H,N,DH]
    sgemm_qkv<<<dim3(MTOT / 128, DIMC / 128, 3), 256>>>(query, key_, value,
                                                        Wq, Wk, Wv);
    // 2) Attention -> [B,N,H*DH]
    attn_kernel<<<dim3(NSEQ / 64, BC * HEADS), 256, ATTN_SMEM>>>();
    // 3) Wo projection + bias
    sgemm_wo<<<dim3(MTOT / 128, DIMC / 128), 256>>>(Wo, bo);
    // 4) LayerNorm + residual
    ln_kernel<<<MTOT, 256>>>(query, gamma, beta, out);
}

// round 7
// speedup vs baseline: 1.4323x; 1.4323x over previous
#include <cuda_runtime.h>
#include <cstdint>

// ---------------------------------------------------------------------------
// MultiHeadAttention: out = LN( softmax(QK^T/sqrt(d)) V @ Wo + bo ) + query
// B=4, N=2048, DIM=1024, HEADS=16, DH=64
// Round-3: 3xTF32 tensor-core (mma.sync m16n8k8) GEMMs + flash attention.
// ---------------------------------------------------------------------------

#define BC    4
#define NSEQ  2048
#define DIMC  1024
#define HEADS 16
#define DHEAD 64
#define MTOT  (BC * NSEQ)   // 8192

// Scratch (device globals: allocation-free per harness rules)
__device__ float g_q[MTOT * DIMC];     // [B,H,N,DH]
__device__ float g_k[MTOT * DIMC];     // [B,H,N,DH]
__device__ float g_v[MTOT * DIMC];     // [B,H,N,DH]
__device__ float g_attn[MTOT * DIMC];  // [B,N,H*DH]
__device__ float g_proj[MTOT * DIMC];  // attn @ Wo + bo

// ---------------------------------------------------------------------------
// tf32 helpers
// ---------------------------------------------------------------------------
__device__ __forceinline__ void split_tf32(float x, uint32_t& hi, uint32_t& lo)
{
    uint32_t h, l;
    asm("cvt.rna.tf32.f32 %0, %1;" : "=r"(h) : "f"(x));
    float r = x - __uint_as_float(h);
    asm("cvt.rna.tf32.f32 %0, %1;" : "=r"(l) : "f"(r));
    hi = h; lo = l;
}

__device__ __forceinline__ void mma8(float* d,
                                     uint32_t a0, uint32_t a1, uint32_t a2, uint32_t a3,
                                     uint32_t b0, uint32_t b1)
{
    asm volatile(
        "mma.sync.aligned.m16n8k8.row.col.f32.tf32.tf32.f32 "
        "{%0,%1,%2,%3}, {%4,%5,%6,%7}, {%8,%9}, {%0,%1,%2,%3};\n"
        : "+f"(d[0]), "+f"(d[1]), "+f"(d[2]), "+f"(d[3])
        : "r"(a0), "r"(a1), "r"(a2), "r"(a3), "r"(b0), "r"(b1));
}

// 3xTF32: d += A*B with hi/lo splits (drop lo*lo term)
__device__ __forceinline__ void mma3(float* d,
                                     const uint32_t* ah, const uint32_t* al,
                                     uint32_t bh0, uint32_t bh1,
                                     uint32_t bl0, uint32_t bl1)
{
    mma8(d, ah[0], ah[1], ah[2], ah[3], bl0, bl1);
    mma8(d, al[0], al[1], al[2], al[3], bh0, bh1);
    mma8(d, ah[0], ah[1], ah[2], ah[3], bh0, bh1);
}

// ---------------------------------------------------------------------------
// Shared GEMM mainloop: 128x128 block tile, BK=32, 256 threads (8 warps 2x4).
// Warp tile 64x32 (4 m-tiles x 4 n-tiles of m16n8).
// As padded ld=36 (conflict-free frag loads), Bs ld=136.
// ---------------------------------------------------------------------------
#define GLDA 36
#define GLDB 136

__device__ __forceinline__ void gemm_mainloop(
    const float* __restrict__ A, const float* __restrict__ W,
    int bm, int bn, float* As, float* Bs, float acc[4][4][4])
{
    const int tid = threadIdx.x;
    const int lane = tid & 31;
    const int warp = tid >> 5;
    const int gid = lane >> 2;
    const int tg = lane & 3;
    const int wm = warp >> 2;   // 0..1
    const int wn = warp & 3;    // 0..3

    float4 pa[4], pb[4];
#pragma unroll
    for (int i = 0; i < 4; i++) {
        int flat = i * 1024 + tid * 4;
        pa[i] = *(const float4*)(A + (bm + (flat >> 5)) * DIMC + (flat & 31));
        pb[i] = *(const float4*)(W + (flat >> 7) * DIMC + bn + (flat & 127));
    }

    for (int kb = 0; kb < DIMC / 32; kb++) {
#pragma unroll
        for (int i = 0; i < 4; i++) {
            int flat = i * 1024 + tid * 4;
            *(float4*)&As[(flat >> 5) * GLDA + (flat & 31)] = pa[i];
            *(float4*)&Bs[(flat >> 7) * GLDB + (flat & 127)] = pb[i];
        }
        __syncthreads();

        if (kb < DIMC / 32 - 1) {
            int k0 = (kb + 1) * 32;
#pragma unroll
            for (int i = 0; i < 4; i++) {
                int flat = i * 1024 + tid * 4;
                pa[i] = *(const float4*)(A + (bm + (flat >> 5)) * DIMC + k0 + (flat & 31));
                pb[i] = *(const float4*)(W + (k0 + (flat >> 7)) * DIMC + bn + (flat & 127));
            }
        }

#pragma unroll
        for (int ks = 0; ks < 4; ks++) {
            const int k = ks * 8;
            uint32_t ah[4][4], al[4][4];
#pragma unroll
            for (int mt = 0; mt < 4; mt++) {
                int r = wm * 64 + mt * 16 + gid;
                split_tf32(As[r * GLDA + k + tg],           ah[mt][0], al[mt][0]);
                split_tf32(As[(r + 8) * GLDA + k + tg],     ah[mt][1], al[mt][1]);
                split_tf32(As[r * GLDA + k + tg + 4],       ah[mt][2], al[mt][2]);
                split_tf32(As[(r + 8) * GLDA + k + tg + 4], ah[mt][3], al[mt][3]);
            }
#pragma unroll
            for (int nt = 0; nt < 4; nt++) {
                int cc = wn * 32 + nt * 8 + gid;
                uint32_t bh0, bl0, bh1, bl1;
                split_tf32(Bs[(k + tg) * GLDB + cc],     bh0, bl0);
                split_tf32(Bs[(k + tg + 4) * GLDB + cc], bh1, bl1);
#pragma unroll
                for (int mt = 0; mt < 4; mt++)
                    mma3(acc[mt][nt], ah[mt], al[mt], bh0, bh1, bl0, bl1);
            }
        }
        __syncthreads();
    }
}

// ---------------------------------------------------------------------------
// QKV projection: C = X @ W scattered into [B,H,N,DH]. which: 0=q,1=k,2=v.
// ---------------------------------------------------------------------------
__global__ __launch_bounds__(256) void mma_gemm_qkv(
    const float* __restrict__ A, const float* __restrict__ W, int which)
{
    __shared__ float As[128 * GLDA];
    __shared__ float Bs[32 * GLDB];
    float* C = (which == 0) ? g_q : (which == 1) ? g_k : g_v;

    const int bm = blockIdx.x * 128;
    const int bn = blockIdx.y * 128;
    float acc[4][4][4];
#pragma unroll
    for (int mt = 0; mt < 4; mt++)
#pragma unroll
        for (int nt = 0; nt < 4; nt++)
#pragma unroll
            for (int c = 0; c < 4; c++) acc[mt][nt][c] = 0.f;

    gemm_mainloop(A, W, bm, bn, As, Bs, acc);

    const int lane = threadIdx.x & 31;
    const int warp = threadIdx.x >> 5;
    const int gid = lane >> 2, tg = lane & 3;
    const int wm = warp >> 2, wn = warp & 3;

#pragma unroll
    for (int mt = 0; mt < 4; mt++) {
        int row = bm + wm * 64 + mt * 16 + gid;
#pragma unroll
        for (int nt = 0; nt < 4; nt++) {
            int col = bn + wn * 32 + nt * 8 + 2 * tg;
            int h = col >> 6, d = col & 63;
#pragma unroll
            for (int half = 0; half < 2; half++) {
                int r = row + half * 8;
                int b = r >> 11, n = r & 2047;
                float2 v = make_float2(acc[mt][nt][2 * half], acc[mt][nt][2 * half + 1]);
                *(float2*)&C[(((size_t)(b * HEADS + h) * NSEQ) + n) * DHEAD + d] = v;
            }
        }
    }
}

// ---------------------------------------------------------------------------
// Wo projection: g_proj = g_attn @ Wo + bo
// ---------------------------------------------------------------------------
__global__ __launch_bounds__(256) void mma_gemm_wo(
    const float* __restrict__ W, const float* __restrict__ bo)
{
    __shared__ float As[128 * GLDA];
    __shared__ float Bs[32 * GLDB];

    const int bm = blockIdx.x * 128;
    const int bn = blockIdx.y * 128;
    float acc[4][4][4];
#pragma unroll
    for (int mt = 0; mt < 4; mt++)
#pragma unroll
        for (int nt = 0; nt < 4; nt++)
#pragma unroll
            for (int c = 0; c < 4; c++) acc[mt][nt][c] = 0.f;

    gemm_mainloop(g_attn, W, bm, bn, As, Bs, acc);

    const int lane = threadIdx.x & 31;
    const int warp = threadIdx.x >> 5;
    const int gid = lane >> 2, tg = lane & 3;
    const int wm = warp >> 2, wn = warp & 3;

#pragma unroll
    for (int mt = 0; mt < 4; mt++) {
        int row = bm + wm * 64 + mt * 16 + gid;
#pragma unroll
        for (int nt = 0; nt < 4; nt++) {
            int col = bn + wn * 32 + nt * 8 + 2 * tg;
            float b0 = bo[col], b1 = bo[col + 1];
#pragma unroll
            for (int half = 0; half < 2; half++) {
                int r = row + half * 8;
                float2 v = make_float2(acc[mt][nt][2 * half] + b0,
                                       acc[mt][nt][2 * half + 1] + b1);
                *(float2*)&g_proj[(size_t)r * DIMC + col] = v;
            }
        }
    }
}

// ---------------------------------------------------------------------------
// Flash attention with 3xTF32 mma. Grid: (N/128, B*H), 128 threads (4 warps).
// Block: 128 query rows; warp owns 32 rows (2 m-tiles). KV tiles of 64.
// smem (dynamic): sQ[128][68] + sK[64][68] + sV[64][72] + sP[128][68]
// Padding gives conflict-free scalar fragment loads.
// ---------------------------------------------------------------------------
#define LQ 68
#define LK 68
#define LV 72
#define LP 68
#define ATTN_SMEM ((128 * LQ + 64 * LK + 64 * LV + 128 * LP) * 4)

__global__ __launch_bounds__(128) void attn_mma()
{
    extern __shared__ float sm[];
    float* sQ = sm;                     // [128][LQ], pre-scaled by 1/8
    float* sK = sQ + 128 * LQ;          // [64][LK]
    float* sV = sK + 64 * LK;           // [64][LV]
    float* sP = sV + 64 * LV;           // [128][LP]

    const int tid = threadIdx.x;
    const int w = tid >> 5;
    const int lane = tid & 31;
    const int gid = lane >> 2, tg = lane & 3;
    const int qt = blockIdx.x;
    const int bh = blockIdx.y;

    const float* Qg = g_q + (size_t)bh * NSEQ * DHEAD + qt * 128 * DHEAD;
    const float* Kg = g_k + (size_t)bh * NSEQ * DHEAD;
    const float* Vg = g_v + (size_t)bh * NSEQ * DHEAD;

    // Load Q (scaled)
#pragma unroll
    for (int i = 0; i < 16; i++) {
        int flat = i * 512 + tid * 4;
        int row = flat >> 6, col = flat & 63;
        float4 v = *(const float4*)(Qg + row * DHEAD + col);
        v.x *= 0.125f; v.y *= 0.125f; v.z *= 0.125f; v.w *= 0.125f;
        *(float4*)&sQ[row * LQ + col] = v;
    }

    float m_[2][2], l_[2][2], o[2][8][4];
#pragma unroll
    for (int mt = 0; mt < 2; mt++)
#pragma unroll
        for (int h = 0; h < 2; h++) { m_[mt][h] = -1e30f; l_[mt][h] = 0.f; }
#pragma unroll
    for (int mt = 0; mt < 2; mt++)
#pragma unroll
        for (int nt = 0; nt < 8; nt++)
#pragma unroll
            for (int c = 0; c < 4; c++) o[mt][nt][c] = 0.f;

    for (int kt = 0; kt < NSEQ / 64; kt++) {
        __syncthreads();   // prev iter done reading sK/sV
#pragma unroll
        for (int i = 0; i < 8; i++) {
            int flat = i * 512 + tid * 4;
            int row = flat >> 6, col = flat & 63;
            *(float4*)&sK[row * LK + col] =
                *(const float4*)(Kg + (kt * 64 + row) * DHEAD + col);
            *(float4*)&sV[row * LV + col] =
                *(const float4*)(Vg + (kt * 64 + row) * DHEAD + col);
        }
        __syncthreads();

        // ---- S = (Q/8) @ K^T ----
        float s[2][8][4];
#pragma unroll
        for (int mt = 0; mt < 2; mt++)
#pragma unroll
            for (int nt = 0; nt < 8; nt++)
#pragma unroll
                for (int c = 0; c < 4; c++) s[mt][nt][c] = 0.f;

#pragma unroll
        for (int ks = 0; ks < 8; ks++) {
            const int k = ks * 8;
            uint32_t ah[2][4], al[2][4];
#pragma unroll
            for (int mt = 0; mt < 2; mt++) {
                int r = w * 32 + mt * 16 + gid;
                split_tf32(sQ[r * LQ + k + tg],           ah[mt][0], al[mt][0]);
                split_tf32(sQ[(r + 8) * LQ + k + tg],     ah[mt][1], al[mt][1]);
                split_tf32(sQ[r * LQ + k + tg + 4],       ah[mt][2], al[mt][2]);
                split_tf32(sQ[(r + 8) * LQ + k + tg + 4], ah[mt][3], al[mt][3]);
            }
#pragma unroll
            for (int nt = 0; nt < 8; nt++) {
                int n = nt * 8 + gid;
                uint32_t bh0, bl0, bh1, bl1;
                split_tf32(sK[n * LK + k + tg],     bh0, bl0);
                split_tf32(sK[n * LK + k + tg + 4], bh1, bl1);
#pragma unroll
                for (int mt = 0; mt < 2; mt++)
                    mma3(s[mt][nt], ah[mt], al[mt], bh0, bh1, bl0, bl1);
            }
        }

        // ---- online softmax (rows live in 4-lane groups) ----
#pragma unroll
        for (int mt = 0; mt < 2; mt++) {
#pragma unroll
            for (int h = 0; h < 2; h++) {
                float mx = -1e30f;
#pragma unroll
                for (int nt = 0; nt < 8; nt++)
                    mx = fmaxf(mx, fmaxf(s[mt][nt][2 * h], s[mt][nt][2 * h + 1]));
                mx = fmaxf(mx, __shfl_xor_sync(0xffffffffu, mx, 1));
                mx = fmaxf(mx, __shfl_xor_sync(0xffffffffu, mx, 2));
                float mnew = fmaxf(m_[mt][h], mx);
                float corr = __expf(m_[mt][h] - mnew);
                m_[mt][h] = mnew;
                int row = w * 32 + mt * 16 + gid + h * 8;
                float rs = 0.f;
#pragma unroll
                for (int nt = 0; nt < 8; nt++) {
                    float p0 = __expf(s[mt][nt][2 * h] - mnew);
                    float p1 = __expf(s[mt][nt][2 * h + 1] - mnew);
                    rs += p0 + p1;
                    *(float2*)&sP[row * LP + nt * 8 + 2 * tg] = make_float2(p0, p1);
                }
                rs += __shfl_xor_sync(0xffffffffu, rs, 1);
                rs += __shfl_xor_sync(0xffffffffu, rs, 2);
                l_[mt][h] = l_[mt][h] * corr + rs;
#pragma unroll
                for (int nt = 0; nt < 8; nt++) {
                    o[mt][nt][2 * h] *= corr;
                    o[mt][nt][2 * h + 1] *= corr;
                }
            }
        }
        __syncwarp();

        // ---- O += P @ V ----
#pragma unroll
        for (int ks = 0; ks < 8; ks++) {
            const int k = ks * 8;
            uint32_t ah[2][4], al[2][4];
#pragma unroll
            for (int mt = 0; mt < 2; mt++) {
                int r = w * 32 + mt * 16 + gid;
                split_tf32(sP[r * LP + k + tg],           ah[mt][0], al[mt][0]);
                split_tf32(sP[(r + 8) * LP + k + tg],     ah[mt][1], al[mt][1]);
                split_tf32(sP[r * LP + k + tg + 4],       ah[mt][2], al[mt][2]);
                split_tf32(sP[(r + 8) * LP + k + tg + 4], ah[mt][3], al[mt][3]);
            }
#pragma unroll
            for (int nt = 0; nt < 8; nt++) {
                int n = nt * 8 + gid;
                uint32_t bh0, bl0, bh1, bl1;
                split_tf32(sV[(k + tg) * LV + n],     bh0, bl0);
                split_tf32(sV[(k + tg + 4) * LV + n], bh1, bl1);
#pragma unroll
                for (int mt = 0; mt < 2; mt++)
                    mma3(o[mt][nt], ah[mt], al[mt], bh0, bh1, bl0, bl1);
            }
        }
    }

    // ---- epilogue: normalize, write [B,N,H*DH] ----
    const int b = bh >> 4;
    const int hh = bh & 15;
#pragma unroll
    for (int mt = 0; mt < 2; mt++) {
#pragma unroll
        for (int half = 0; half < 2; half++) {
            float inv = 1.0f / l_[mt][half];
            int n = qt * 128 + w * 32 + mt * 16 + gid + half * 8;
#pragma unroll
            for (int nt = 0; nt < 8; nt++) {
                int col = hh * DHEAD + nt * 8 + 2 * tg;
                float2 v = make_float2(o[mt][nt][2 * half] * inv,
                                       o[mt][nt][2 * half + 1] * inv);
                *(float2*)&g_attn[((size_t)b * NSEQ + n) * DIMC + col] = v;
            }
        }
    }
}

// ---------------------------------------------------------------------------
// LayerNorm over last dim + residual. One block per row.
// ---------------------------------------------------------------------------
__global__ __launch_bounds__(256) void ln_kernel(
    const float* __restrict__ query, const float* __restrict__ gamma,
    const float* __restrict__ beta, float* __restrict__ out)
{
    const int r = blockIdx.x;
    const float* x = g_proj + (size_t)r * DIMC;

    float v[4];
    float s = 0.f, ss = 0.f;
#pragma unroll
    for (int i = 0; i < 4; i++) {
        v[i] = x[threadIdx.x + 256 * i];
        s += v[i];
        ss += v[i] * v[i];
    }
#pragma unroll
    for (int ofs = 16; ofs > 0; ofs >>= 1) {
        s  += __shfl_xor_sync(0xffffffffu, s,  ofs);
        ss += __shfl_xor_sync(0xffffffffu, ss, ofs);
    }
    __shared__ float rs[8], rss[8];
    int w = threadIdx.x >> 5, lane = threadIdx.x & 31;
    if (lane == 0) { rs[w] = s; rss[w] = ss; }
    __syncthreads();
    if (threadIdx.x == 0) {
        float a = 0.f, b2 = 0.f;
#pragma unroll
        for (int i = 0; i < 8; i++) { a += rs[i]; b2 += rss[i]; }
        rs[0] = a; rss[0] = b2;
    }
    __syncthreads();
    const float mean = rs[0] * (1.0f / DIMC);
    const float var  = rss[0] * (1.0f / DIMC) - mean * mean;
    const float inv  = rsqrtf(var + 1e-5f);

#pragma unroll
    for (int i = 0; i < 4; i++) {
        int c = threadIdx.x + 256 * i;
        size_t idx = (size_t)r * DIMC + c;
        out[idx] = (v[i] - mean) * inv * gamma[c] + beta[c] + query[idx];
    }
}

// ---------------------------------------------------------------------------
extern "C" void kernel_launch(void* const* d_in, const int* in_sizes, int n_in,
                              void* d_out, int out_size)
{
    const float* query = (const float*)d_in[0];
    const float* key_  = (const float*)d_in[1];
    const float* value = (const float*)d_in[2];
    const float* Wq    = (const float*)d_in[3];
    const float* Wk    = (const float*)d_in[4];
    const float* Wv    = (const float*)d_in[5];
    const float* Wo    = (const float*)d_in[6];
    const float* bo    = (const float*)d_in[7];
    const float* gamma = (const float*)d_in[8];
    const float* beta  = (const float*)d_in[9];
    float* out = (float*)d_out;

    cudaFuncSetAttribute(attn_mma,
                         cudaFuncAttributeMaxDynamicSharedMemorySize, ATTN_SMEM);

    dim3 ggrid(MTOT / 128, DIMC / 128);
    // 1) QKV projections -> [B,H,N,DH]
    mma_gemm_qkv<<<ggrid, 256>>>(query, Wq, 0);
    mma_gemm_qkv<<<ggrid, 256>>>(key_,  Wk, 1);
    mma_gemm_qkv<<<ggrid, 256>>>(value, Wv, 2);
    // 2) Attention -> [B,N,H*DH]
    attn_mma<<<dim3(NSEQ / 128, BC * HEADS), 128, ATTN_SMEM>>>();
    // 3) Wo projection + bias
    mma_gemm_wo<<<ggrid, 256>>>(Wo, bo);
    // 4) LayerNorm + residual
    ln_kernel<<<MTOT, 256>>>(query, gamma, beta, out);
}

// round 8
// speedup vs baseline: 2.5391x; 1.7728x over previous
#include <cuda_runtime.h>
#include <cstdint>

// ---------------------------------------------------------------------------
// MultiHeadAttention: out = LN( softmax(QK^T/sqrt(d)) V @ Wo + bo ) + query
// B=4, N=2048, DIM=1024, HEADS=16, DH=64
// Round-7: bf16-split (3-term) mma.sync m16n8k16; splits precomputed in smem.
// ---------------------------------------------------------------------------

#define BC    4
#define NSEQ  2048
#define DIMC  1024
#define HEADS 16
#define DHEAD 64
#define MTOT  (BC * NSEQ)   // 8192

__device__ float g_q[MTOT * DIMC];     // [B,H,N,DH]
__device__ float g_k[MTOT * DIMC];     // [B,H,N,DH]
__device__ float g_v[MTOT * DIMC];     // [B,H,N,DH]
__device__ float g_attn[MTOT * DIMC];  // [B,N,H*DH]
__device__ float g_proj[MTOT * DIMC];  // attn @ Wo + bo

// ---------------------------------------------------------------------------
// bf16 split helpers: x = hi + lo, both bf16; packed as bf16x2 (low = elem k)
// ---------------------------------------------------------------------------
__device__ __forceinline__ uint32_t pack_bf2(float x0, float x1)
{
    uint32_t p;
    asm("cvt.rn.satfinite.bf16x2.f32 %0, %1, %2;" : "=r"(p) : "f"(x1), "f"(x0));
    return p;
}

__device__ __forceinline__ void split_bf2(float x0, float x1,
                                          uint32_t& hi, uint32_t& lo)
{
    uint32_t h = pack_bf2(x0, x1);
    float h0 = __uint_as_float(h << 16);
    float h1 = __uint_as_float(h & 0xffff0000u);
    lo = pack_bf2(x0 - h0, x1 - h1);
    hi = h;
}

__device__ __forceinline__ void mma16(float* d,
                                      uint32_t a0, uint32_t a1, uint32_t a2, uint32_t a3,
                                      uint32_t b0, uint32_t b1)
{
    asm volatile(
        "mma.sync.aligned.m16n8k16.row.col.f32.bf16.bf16.f32 "
        "{%0,%1,%2,%3}, {%4,%5,%6,%7}, {%8,%9}, {%0,%1,%2,%3};\n"
        : "+f"(d[0]), "+f"(d[1]), "+f"(d[2]), "+f"(d[3])
        : "r"(a0), "r"(a1), "r"(a2), "r"(a3), "r"(b0), "r"(b1));
}

// 3-term: D += Ah*Bl + Al*Bh + Ah*Bh  (low-order terms first)
__device__ __forceinline__ void mma3(float* d,
                                     const uint32_t* ah, const uint32_t* al,
                                     uint32_t bh0, uint32_t bh1,
                                     uint32_t bl0, uint32_t bl1)
{
    mma16(d, ah[0], ah[1], ah[2], ah[3], bl0, bl1);
    mma16(d, al[0], al[1], al[2], al[3], bh0, bh1);
    mma16(d, ah[0], ah[1], ah[2], ah[3], bh0, bh1);
}

// ---------------------------------------------------------------------------
// GEMM: 128x128 block, BK=32, 256 threads (8 warps 2x4), warp tile 64x32.
// A smem: row-major pairs [128 rows][20 kp-words] (pitch 20 -> frag loads CF)
// B smem: kp-major [16 kp][136 n-words]   (pitch 136 -> frag loads CF)
// ---------------------------------------------------------------------------
#define GAP 20
#define GBP 136

__device__ __forceinline__ void gemm_mainloop(
    const float* __restrict__ A, const float* __restrict__ W,
    int bm, int bn,
    uint32_t* sAh, uint32_t* sAl, uint32_t* sBh, uint32_t* sBl,
    float acc[4][4][4])
{
    const int tid = threadIdx.x;
    const int lane = tid & 31;
    const int warp = tid >> 5;
    const int gid = lane >> 2;
    const int tg = lane & 3;
    const int wm = warp >> 2;   // 0..1
    const int wn = warp & 3;    // 0..3

    // B loader coords: thread covers one kp (pair of k rows), 8 n cols
    const int bkp = tid >> 4;           // 0..15
    const int bn0 = (tid & 15) * 8;     // 0..120

    float4 pa[4], pb[4];
#pragma unroll
    for (int i = 0; i < 4; i++) {
        int flat = i * 1024 + tid * 4;
        pa[i] = *(const float4*)(A + (bm + (flat >> 5)) * DIMC + (flat & 31));
    }
    pb[0] = *(const float4*)(W + (2 * bkp) * DIMC + bn + bn0);
    pb[1] = *(const float4*)(W + (2 * bkp) * DIMC + bn + bn0 + 4);
    pb[2] = *(const float4*)(W + (2 * bkp + 1) * DIMC + bn + bn0);
    pb[3] = *(const float4*)(W + (2 * bkp + 1) * DIMC + bn + bn0 + 4);

    for (int kb = 0; kb < DIMC / 32; kb++) {
        // ---- store A (pairs along k) ----
#pragma unroll
        for (int i = 0; i < 4; i++) {
            int flat = i * 1024 + tid * 4;
            int row = flat >> 5, kp = (flat & 31) >> 1;
            uint32_t h0, l0, h1, l1;
            split_bf2(pa[i].x, pa[i].y, h0, l0);
            split_bf2(pa[i].z, pa[i].w, h1, l1);
            uint2 uh; uh.x = h0; uh.y = h1;
            uint2 ul; ul.x = l0; ul.y = l1;
            *(uint2*)&sAh[row * GAP + kp] = uh;
            *(uint2*)&sAl[row * GAP + kp] = ul;
        }
        // ---- store B (pairs across the two k rows) ----
        {
            const float* r0 = &pb[0].x;   // pb[0],pb[1] = row 2kp
            const float* r1 = &pb[2].x;   // pb[2],pb[3] = row 2kp+1
            uint32_t hh[8], ll[8];
#pragma unroll
            for (int j = 0; j < 8; j++)
                split_bf2(r0[j], r1[j], hh[j], ll[j]);
            *(uint4*)&sBh[bkp * GBP + bn0]     = *(uint4*)&hh[0];
            *(uint4*)&sBh[bkp * GBP + bn0 + 4] = *(uint4*)&hh[4];
            *(uint4*)&sBl[bkp * GBP + bn0]     = *(uint4*)&ll[0];
            *(uint4*)&sBl[bkp * GBP + bn0 + 4] = *(uint4*)&ll[4];
        }
        __syncthreads();

        if (kb < DIMC / 32 - 1) {
            int k0 = (kb + 1) * 32;
#pragma unroll
            for (int i = 0; i < 4; i++) {
                int flat = i * 1024 + tid * 4;
                pa[i] = *(const float4*)(A + (bm + (flat >> 5)) * DIMC + k0 + (flat & 31));
            }
            pb[0] = *(const float4*)(W + (k0 + 2 * bkp) * DIMC + bn + bn0);
            pb[1] = *(const float4*)(W + (k0 + 2 * bkp) * DIMC + bn + bn0 + 4);
            pb[2] = *(const float4*)(W + (k0 + 2 * bkp + 1) * DIMC + bn + bn0);
            pb[3] = *(const float4*)(W + (k0 + 2 * bkp + 1) * DIMC + bn + bn0 + 4);
        }

#pragma unroll
        for (int ks = 0; ks < 2; ks++) {
            const int kp0 = ks * 8;
            uint32_t ah[4][4], al[4][4];
#pragma unroll
            for (int mt = 0; mt < 4; mt++) {
                int r = wm * 64 + mt * 16 + gid;
                ah[mt][0] = sAh[r * GAP + kp0 + tg];
                ah[mt][1] = sAh[(r + 8) * GAP + kp0 + tg];
                ah[mt][2] = sAh[r * GAP + kp0 + 4 + tg];
                ah[mt][3] = sAh[(r + 8) * GAP + kp0 + 4 + tg];
                al[mt][0] = sAl[r * GAP + kp0 + tg];
                al[mt][1] = sAl[(r + 8) * GAP + kp0 + tg];
                al[mt][2] = sAl[r * GAP + kp0 + 4 + tg];
                al[mt][3] = sAl[(r + 8) * GAP + kp0 + 4 + tg];
            }
#pragma unroll
            for (int nt = 0; nt < 4; nt++) {
                int c = wn * 32 + nt * 8 + gid;
                uint32_t bh0 = sBh[(kp0 + tg) * GBP + c];
                uint32_t bh1 = sBh[(kp0 + 4 + tg) * GBP + c];
                uint32_t bl0 = sBl[(kp0 + tg) * GBP + c];
                uint32_t bl1 = sBl[(kp0 + 4 + tg) * GBP + c];
#pragma unroll
                for (int mt = 0; mt < 4; mt++)
                    mma3(acc[mt][nt], ah[mt], al[mt], bh0, bh1, bl0, bl1);
            }
        }
        __syncthreads();
    }
}

// ---------------------------------------------------------------------------
// QKV projection: C = X @ W scattered into [B,H,N,DH]. which: 0=q,1=k,2=v.
// ---------------------------------------------------------------------------
__global__ __launch_bounds__(256) void mma_gemm_qkv(
    const float* __restrict__ A, const float* __restrict__ W, int which)
{
    __shared__ __align__(16) uint32_t sAh[128 * GAP], sAl[128 * GAP];
    __shared__ __align__(16) uint32_t sBh[16 * GBP], sBl[16 * GBP];
    float* C = (which == 0) ? g_q : (which == 1) ? g_k : g_v;

    const int bm = blockIdx.x * 128;
    const int bn = blockIdx.y * 128;
    float acc[4][4][4];
#pragma unroll
    for (int mt = 0; mt < 4; mt++)
#pragma unroll
        for (int nt = 0; nt < 4; nt++)
#pragma unroll
            for (int c = 0; c < 4; c++) acc[mt][nt][c] = 0.f;

    gemm_mainloop(A, W, bm, bn, sAh, sAl, sBh, sBl, acc);

    const int lane = threadIdx.x & 31;
    const int warp = threadIdx.x >> 5;
    const int gid = lane >> 2, tg = lane & 3;
    const int wm = warp >> 2, wn = warp & 3;

#pragma unroll
    for (int mt = 0; mt < 4; mt++) {
        int row = bm + wm * 64 + mt * 16 + gid;
#pragma unroll
        for (int nt = 0; nt < 4; nt++) {
            int col = bn + wn * 32 + nt * 8 + 2 * tg;
            int h = col >> 6, d = col & 63;
#pragma unroll
            for (int half = 0; half < 2; half++) {
                int r = row + half * 8;
                int b = r >> 11, n = r & 2047;
                float2 v = make_float2(acc[mt][nt][2 * half], acc[mt][nt][2 * half + 1]);
                *(float2*)&C[(((size_t)(b * HEADS + h) * NSEQ) + n) * DHEAD + d] = v;
            }
        }
    }
}

// ---------------------------------------------------------------------------
// Wo projection: g_proj = g_attn @ Wo + bo
// ---------------------------------------------------------------------------
__global__ __launch_bounds__(256) void mma_gemm_wo(
    const float* __restrict__ W, const float* __restrict__ bo)
{
    __shared__ __align__(16) uint32_t sAh[128 * GAP], sAl[128 * GAP];
    __shared__ __align__(16) uint32_t sBh[16 * GBP], sBl[16 * GBP];

    const int bm = blockIdx.x * 128;
    const int bn = blockIdx.y * 128;
    float acc[4][4][4];
#pragma unroll
    for (int mt = 0; mt < 4; mt++)
#pragma unroll
        for (int nt = 0; nt < 4; nt++)
#pragma unroll
            for (int c = 0; c < 4; c++) acc[mt][nt][c] = 0.f;

    gemm_mainloop(g_attn, W, bm, bn, sAh, sAl, sBh, sBl, acc);

    const int lane = threadIdx.x & 31;
    const int warp = threadIdx.x >> 5;
    const int gid = lane >> 2, tg = lane & 3;
    const int wm = warp >> 2, wn = warp & 3;

#pragma unroll
    for (int mt = 0; mt < 4; mt++) {
        int row = bm + wm * 64 + mt * 16 + gid;
#pragma unroll
        for (int nt = 0; nt < 4; nt++) {
            int col = bn + wn * 32 + nt * 8 + 2 * tg;
            float b0 = bo[col], b1 = bo[col + 1];
#pragma unroll
            for (int half = 0; half < 2; half++) {
                int r = row + half * 8;
                float2 v = make_float2(acc[mt][nt][2 * half] + b0,
                                       acc[mt][nt][2 * half + 1] + b1);
                *(float2*)&g_proj[(size_t)r * DIMC + col] = v;
            }
        }
    }
}

// ---------------------------------------------------------------------------
// Flash attention, bf16-split mma. Grid: (N/128, B*H), 128 threads (4 warps).
// Warp owns 32 q rows (2 m-tiles). KV tiles of 64.
// Layouts (u32 words, pair-packed bf16x2 along k):
//   sQ: [128 q][36]   (row-major pairs, k = headdim)
//   sK: [64 kv][36]   (row-major pairs, k = headdim)
//   sV: [32 kvp][72]  (kp-major, k = kv sequence)
//   sP: [128 q][36]   (row-major pairs, k = kv sequence)
// ---------------------------------------------------------------------------
#define AQP 36
#define AKP 36
#define AVP 72
#define APP 36
#define QW  (128 * AQP)
#define KW  (64 * AKP)
#define VW  (32 * AVP)
#define PW  (128 * APP)
#define ATTN_SMEM ((2 * (QW + KW + VW + PW)) * 4)

__global__ __launch_bounds__(128) void attn_mma()
{
    extern __shared__ __align__(16) uint32_t smw[];
    uint32_t* sQh = smw;
    uint32_t* sQl = sQh + QW;
    uint32_t* sKh = sQl + QW;
    uint32_t* sKl = sKh + KW;
    uint32_t* sVh = sKl + KW;
    uint32_t* sVl = sVh + VW;
    uint32_t* sPh = sVl + VW;
    uint32_t* sPl = sPh + PW;

    const int tid = threadIdx.x;
    const int w = tid >> 5;
    const int lane = tid & 31;
    const int gid = lane >> 2, tg = lane & 3;
    const int qt = blockIdx.x;
    const int bh = blockIdx.y;

    const float* Qg = g_q + (size_t)bh * NSEQ * DHEAD + qt * 128 * DHEAD;
    const float* Kg = g_k + (size_t)bh * NSEQ * DHEAD;
    const float* Vg = g_v + (size_t)bh * NSEQ * DHEAD;

    // ---- load Q, pre-scaled, split to bf16 pairs ----
#pragma unroll
    for (int i = 0; i < 16; i++) {
        int flat = i * 512 + tid * 4;
        int row = flat >> 6, d = flat & 63, kp = d >> 1;
        float4 v = *(const float4*)(Qg + row * DHEAD + d);
        v.x *= 0.125f; v.y *= 0.125f; v.z *= 0.125f; v.w *= 0.125f;
        uint32_t h0, l0, h1, l1;
        split_bf2(v.x, v.y, h0, l0);
        split_bf2(v.z, v.w, h1, l1);
        uint2 uh; uh.x = h0; uh.y = h1;
        uint2 ul; ul.x = l0; ul.y = l1;
        *(uint2*)&sQh[row * AQP + kp] = uh;
        *(uint2*)&sQl[row * AQP + kp] = ul;
    }

    float m_[2][2], l_[2][2], o[2][8][4];
#pragma unroll
    for (int mt = 0; mt < 2; mt++)
#pragma unroll
        for (int h = 0; h < 2; h++) { m_[mt][h] = -1e30f; l_[mt][h] = 0.f; }
#pragma unroll
    for (int mt = 0; mt < 2; mt++)
#pragma unroll
        for (int nt = 0; nt < 8; nt++)
#pragma unroll
            for (int c = 0; c < 4; c++) o[mt][nt][c] = 0.f;

    for (int kt = 0; kt < NSEQ / 64; kt++) {
        __syncthreads();   // prev iter done reading sK/sV
        // ---- K tile: pairs along d ----
#pragma unroll
        for (int i = 0; i < 8; i++) {
            int flat = i * 512 + tid * 4;
            int kv = flat >> 6, d = flat & 63, kp = d >> 1;
            float4 v = *(const float4*)(Kg + (kt * 64 + kv) * DHEAD + d);
            uint32_t h0, l0, h1, l1;
            split_bf2(v.x, v.y, h0, l0);
            split_bf2(v.z, v.w, h1, l1);
            uint2 uh; uh.x = h0; uh.y = h1;
            uint2 ul; ul.x = l0; ul.y = l1;
            *(uint2*)&sKh[kv * AKP + kp] = uh;
            *(uint2*)&sKl[kv * AKP + kp] = ul;
        }
        // ---- V tile: pairs along kv (cross-row) ----
#pragma unroll
        for (int i = 0; i < 4; i++) {
            int task = i * 128 + tid;
            int kvp = task >> 4, d0 = (task & 15) * 4;
            float4 v0 = *(const float4*)(Vg + (kt * 64 + 2 * kvp) * DHEAD + d0);
            float4 v1 = *(const float4*)(Vg + (kt * 64 + 2 * kvp + 1) * DHEAD + d0);
            uint32_t hh[4], ll[4];
            split_bf2(v0.x, v1.x, hh[0], ll[0]);
            split_bf2(v0.y, v1.y, hh[1], ll[1]);
            split_bf2(v0.z, v1.z, hh[2], ll[2]);
            split_bf2(v0.w, v1.w, hh[3], ll[3]);
            *(uint4*)&sVh[kvp * AVP + d0] = *(uint4*)&hh[0];
            *(uint4*)&sVl[kvp * AVP + d0] = *(uint4*)&ll[0];
        }
        __syncthreads();

        // ---- S = (Q/8) @ K^T ----
        float s[2][8][4];
#pragma unroll
        for (int mt = 0; mt < 2; mt++)
#pragma unroll
            for (int nt = 0; nt < 8; nt++)
#pragma unroll
                for (int c = 0; c < 4; c++) s[mt][nt][c] = 0.f;

#pragma unroll
        for (int ks = 0; ks < 4; ks++) {
            const int kp0 = ks * 8;
            uint32_t ah[2][4], al[2][4];
#pragma unroll
            for (int mt = 0; mt < 2; mt++) {
                int r = w * 32 + mt * 16 + gid;
                ah[mt][0] = sQh[r * AQP + kp0 + tg];
                ah[mt][1] = sQh[(r + 8) * AQP + kp0 + tg];
                ah[mt][2] = sQh[r * AQP + kp0 + 4 + tg];
                ah[mt][3] = sQh[(r + 8) * AQP + kp0 + 4 + tg];
                al[mt][0] = sQl[r * AQP + kp0 + tg];
                al[mt][1] = sQl[(r + 8) * AQP + kp0 + tg];
                al[mt][2] = sQl[r * AQP + kp0 + 4 + tg];
                al[mt][3] = sQl[(r + 8) * AQP + kp0 + 4 + tg];
            }
#pragma unroll
            for (int nt = 0; nt < 8; nt++) {
                int c = nt * 8 + gid;
                uint32_t bh0 = sKh[c * AKP + kp0 + tg];
                uint32_t bh1 = sKh[c * AKP + kp0 + 4 + tg];
                uint32_t bl0 = sKl[c * AKP + kp0 + tg];
                uint32_t bl1 = sKl[c * AKP + kp0 + 4 + tg];
#pragma unroll
                for (int mt = 0; mt < 2; mt++)
                    mma3(s[mt][nt], ah[mt], al[mt], bh0, bh1, bl0, bl1);
            }
        }

        // ---- online softmax; P written as bf16 hi/lo pairs ----
#pragma unroll
        for (int mt = 0; mt < 2; mt++) {
#pragma unroll
            for (int h = 0; h < 2; h++) {
                float mx = -1e30f;
#pragma unroll
                for (int nt = 0; nt < 8; nt++)
                    mx = fmaxf(mx, fmaxf(s[mt][nt][2 * h], s[mt][nt][2 * h + 1]));
                mx = fmaxf(mx, __shfl_xor_sync(0xffffffffu, mx, 1));
                mx = fmaxf(mx, __shfl_xor_sync(0xffffffffu, mx, 2));
                float mnew = fmaxf(m_[mt][h], mx);
                float corr = __expf(m_[mt][h] - mnew);
                m_[mt][h] = mnew;
                int row = w * 32 + mt * 16 + gid + h * 8;
                float rs = 0.f;
#pragma unroll
                for (int nt = 0; nt < 8; nt++) {
                    float p0 = __expf(s[mt][nt][2 * h] - mnew);
                    float p1 = __expf(s[mt][nt][2 * h + 1] - mnew);
                    rs += p0 + p1;
                    uint32_t ph, pl;
                    split_bf2(p0, p1, ph, pl);
                    sPh[row * APP + nt * 4 + tg] = ph;
                    sPl[row * APP + nt * 4 + tg] = pl;
                }
                rs += __shfl_xor_sync(0xffffffffu, rs, 1);
                rs += __shfl_xor_sync(0xffffffffu, rs, 2);
                l_[mt][h] = l_[mt][h] * corr + rs;
#pragma unroll
                for (int nt = 0; nt < 8; nt++) {
                    o[mt][nt][2 * h] *= corr;
                    o[mt][nt][2 * h + 1] *= corr;
                }
            }
        }
        __syncwarp();   // sP is warp-private (rows owned by this warp)

        // ---- O += P @ V ----
#pragma unroll
        for (int ks = 0; ks < 4; ks++) {
            const int kp0 = ks * 8;
            uint32_t ah[2][4], al[2][4];
#pragma unroll
            for (int mt = 0; mt < 2; mt++) {
                int r = w * 32 + mt * 16 + gid;
                ah[mt][0] = sPh[r * APP + kp0 + tg];
                ah[mt][1] = sPh[(r + 8) * APP + kp0 + tg];
                ah[mt][2] = sPh[r * APP + kp0 + 4 + tg];
                ah[mt][3] = sPh[(r + 8) * APP + kp0 + 4 + tg];
                al[mt][0] = sPl[r * APP + kp0 + tg];
                al[mt][1] = sPl[(r + 8) * APP + kp0 + tg];
                al[mt][2] = sPl[r * APP + kp0 + 4 + tg];
                al[mt][3] = sPl[(r + 8) * APP + kp0 + 4 + tg];
            }
#pragma unroll
            for (int nt = 0; nt < 8; nt++) {
                int d = nt * 8 + gid;
                uint32_t bh0 = sVh[(kp0 + tg) * AVP + d];
                uint32_t bh1 = sVh[(kp0 + 4 + tg) * AVP + d];
                uint32_t bl0 = sVl[(kp0 + tg) * AVP + d];
                uint32_t bl1 = sVl[(kp0 + 4 + tg) * AVP + d];
#pragma unroll
                for (int mt = 0; mt < 2; mt++)
                    mma3(o[mt][nt], ah[mt], al[mt], bh0, bh1, bl0, bl1);
            }
        }
    }

    // ---- epilogue: normalize, write [B,N,H*DH] ----
    const int b = bh >> 4;
    const int hh = bh & 15;
#pragma unroll
    for (int mt = 0; mt < 2; mt++) {
#pragma unroll
        for (int half = 0; half < 2; half++) {
            float inv = 1.0f / l_[mt][half];
            int n = qt * 128 + w * 32 + mt * 16 + gid + half * 8;
#pragma unroll
            for (int nt = 0; nt < 8; nt++) {
                int col = hh * DHEAD + nt * 8 + 2 * tg;
                float2 v = make_float2(o[mt][nt][2 * half] * inv,
                                       o[mt][nt][2 * half + 1] * inv);
                *(float2*)&g_attn[((size_t)b * NSEQ + n) * DIMC + col] = v;
            }
        }
    }
}

// ---------------------------------------------------------------------------
// LayerNorm over last dim + residual. One block per row.
// ---------------------------------------------------------------------------
__global__ __launch_bounds__(256) void ln_kernel(
    const float* __restrict__ query, const float* __restrict__ gamma,
    const float* __restrict__ beta, float* __restrict__ out)
{
    const int r = blockIdx.x;
    const float* x = g_proj + (size_t)r * DIMC;

    float v[4];
    float s = 0.f, ss = 0.f;
#pragma unroll
    for (int i = 0; i < 4; i++) {
        v[i] = x[threadIdx.x + 256 * i];
        s += v[i];
        ss += v[i] * v[i];
    }
#pragma unroll
    for (int ofs = 16; ofs > 0; ofs >>= 1) {
        s  += __shfl_xor_sync(0xffffffffu, s,  ofs);
        ss += __shfl_xor_sync(0xffffffffu, ss, ofs);
    }
    __shared__ float rs[8], rss[8];
    int w = threadIdx.x >> 5, lane = threadIdx.x & 31;
    if (lane == 0) { rs[w] = s; rss[w] = ss; }
    __syncthreads();
    if (threadIdx.x == 0) {
        float a = 0.f, b2 = 0.f;
#pragma unroll
        for (int i = 0; i < 8; i++) { a += rs[i]; b2 += rss[i]; }
        rs[0] = a; rss[0] = b2;
    }
    __syncthreads();
    const float mean = rs[0] * (1.0f / DIMC);
    const float var  = rss[0] * (1.0f / DIMC) - mean * mean;
    const float inv  = rsqrtf(var + 1e-5f);

#pragma unroll
    for (int i = 0; i < 4; i++) {
        int c = threadIdx.x + 256 * i;
        size_t idx = (size_t)r * DIMC + c;
        out[idx] = (v[i] - mean) * inv * gamma[c] + beta[c] + query[idx];
    }
}

// ---------------------------------------------------------------------------
extern "C" void kernel_launch(void* const* d_in, const int* in_sizes, int n_in,
                              void* d_out, int out_size)
{
    const float* query = (const float*)d_in[0];
    const float* key_  = (const float*)d_in[1];
    const float* value = (const float*)d_in[2];
    const float* Wq    = (const float*)d_in[3];
    const float* Wk    = (const float*)d_in[4];
    const float* Wv    = (const float*)d_in[5];
    const float* Wo    = (const float*)d_in[6];
    const float* bo    = (const float*)d_in[7];
    const float* gamma = (const float*)d_in[8];
    const float* beta  = (const float*)d_in[9];
    float* out = (float*)d_out;

    cudaFuncSetAttribute(attn_mma,
                         cudaFuncAttributeMaxDynamicSharedMemorySize, ATTN_SMEM);

    dim3 ggrid(MTOT / 128, DIMC / 128);
    // 1) QKV projections -> [B,H,N,DH]
    mma_gemm_qkv<<<ggrid, 256>>>(query, Wq, 0);
    mma_gemm_qkv<<<ggrid, 256>>>(key_,  Wk, 1);
    mma_gemm_qkv<<<ggrid, 256>>>(value, Wv, 2);
    // 2) Attention -> [B,N,H*DH]
    attn_mma<<<dim3(NSEQ / 128, BC * HEADS), 128, ATTN_SMEM>>>();
    // 3) Wo projection + bias
    mma_gemm_wo<<<ggrid, 256>>>(Wo, bo);
    // 4) LayerNorm + residual
    ln_kernel<<<MTOT, 256>>>(query, gamma, beta, out);
}

// round 9
// speedup vs baseline: 2.6947x; 1.0613x over previous
#include <cuda_runtime.h>
#include <cstdint>

// ---------------------------------------------------------------------------
// MultiHeadAttention: out = LN( softmax(QK^T/sqrt(d)) V @ Wo + bo ) + query
// B=4, N=2048, DIM=1024, HEADS=16, DH=64
// Round-8: bf16-split mma; attention restructured: 8 warps, P-in-registers,
// Q fragments hoisted, 72KB smem -> 2 CTAs/SM.
// ---------------------------------------------------------------------------

#define BC    4
#define NSEQ  2048
#define DIMC  1024
#define HEADS 16
#define DHEAD 64
#define MTOT  (BC * NSEQ)   // 8192

__device__ float g_q[MTOT * DIMC];     // [B,H,N,DH]
__device__ float g_k[MTOT * DIMC];     // [B,H,N,DH]
__device__ float g_v[MTOT * DIMC];     // [B,H,N,DH]
__device__ float g_attn[MTOT * DIMC];  // [B,N,H*DH]
__device__ float g_proj[MTOT * DIMC];  // attn @ Wo + bo

// ---------------------------------------------------------------------------
// bf16 split helpers: x = hi + lo, both bf16; packed as bf16x2 (low = elem k)
// ---------------------------------------------------------------------------
__device__ __forceinline__ uint32_t pack_bf2(float x0, float x1)
{
    uint32_t p;
    asm("cvt.rn.satfinite.bf16x2.f32 %0, %1, %2;" : "=r"(p) : "f"(x1), "f"(x0));
    return p;
}

__device__ __forceinline__ void split_bf2(float x0, float x1,
                                          uint32_t& hi, uint32_t& lo)
{
    uint32_t h = pack_bf2(x0, x1);
    float h0 = __uint_as_float(h << 16);
    float h1 = __uint_as_float(h & 0xffff0000u);
    lo = pack_bf2(x0 - h0, x1 - h1);
    hi = h;
}

__device__ __forceinline__ void mma16(float* d,
                                      uint32_t a0, uint32_t a1, uint32_t a2, uint32_t a3,
                                      uint32_t b0, uint32_t b1)
{
    asm volatile(
        "mma.sync.aligned.m16n8k16.row.col.f32.bf16.bf16.f32 "
        "{%0,%1,%2,%3}, {%4,%5,%6,%7}, {%8,%9}, {%0,%1,%2,%3};\n"
        : "+f"(d[0]), "+f"(d[1]), "+f"(d[2]), "+f"(d[3])
        : "r"(a0), "r"(a1), "r"(a2), "r"(a3), "r"(b0), "r"(b1));
}

// 3-term: D += Ah*Bl + Al*Bh + Ah*Bh  (low-order terms first)
__device__ __forceinline__ void mma3(float* d,
                                     const uint32_t* ah, const uint32_t* al,
                                     uint32_t bh0, uint32_t bh1,
                                     uint32_t bl0, uint32_t bl1)
{
    mma16(d, ah[0], ah[1], ah[2], ah[3], bl0, bl1);
    mma16(d, al[0], al[1], al[2], al[3], bh0, bh1);
    mma16(d, ah[0], ah[1], ah[2], ah[3], bh0, bh1);
}

// ---------------------------------------------------------------------------
// GEMM: 128x128 block, BK=32, 256 threads (8 warps 2x4), warp tile 64x32.
// A smem: row-major pairs [128 rows][20 kp-words]; B smem: [16 kp][136 n].
// ---------------------------------------------------------------------------
#define GAP 20
#define GBP 136

__device__ __forceinline__ void gemm_mainloop(
    const float* __restrict__ A, const float* __restrict__ W,
    int bm, int bn,
    uint32_t* sAh, uint32_t* sAl, uint32_t* sBh, uint32_t* sBl,
    float acc[4][4][4])
{
    const int tid = threadIdx.x;
    const int lane = tid & 31;
    const int warp = tid >> 5;
    const int gid = lane >> 2;
    const int tg = lane & 3;
    const int wm = warp >> 2;   // 0..1
    const int wn = warp & 3;    // 0..3

    const int bkp = tid >> 4;           // 0..15
    const int bn0 = (tid & 15) * 8;     // 0..120

    float4 pa[4], pb[4];
#pragma unroll
    for (int i = 0; i < 4; i++) {
        int flat = i * 1024 + tid * 4;
        pa[i] = *(const float4*)(A + (bm + (flat >> 5)) * DIMC + (flat & 31));
    }
    pb[0] = *(const float4*)(W + (2 * bkp) * DIMC + bn + bn0);
    pb[1] = *(const float4*)(W + (2 * bkp) * DIMC + bn + bn0 + 4);
    pb[2] = *(const float4*)(W + (2 * bkp + 1) * DIMC + bn + bn0);
    pb[3] = *(const float4*)(W + (2 * bkp + 1) * DIMC + bn + bn0 + 4);

    for (int kb = 0; kb < DIMC / 32; kb++) {
#pragma unroll
        for (int i = 0; i < 4; i++) {
            int flat = i * 1024 + tid * 4;
            int row = flat >> 5, kp = (flat & 31) >> 1;
            uint32_t h0, l0, h1, l1;
            split_bf2(pa[i].x, pa[i].y, h0, l0);
            split_bf2(pa[i].z, pa[i].w, h1, l1);
            uint2 uh; uh.x = h0; uh.y = h1;
            uint2 ul; ul.x = l0; ul.y = l1;
            *(uint2*)&sAh[row * GAP + kp] = uh;
            *(uint2*)&sAl[row * GAP + kp] = ul;
        }
        {
            const float* r0 = &pb[0].x;
            const float* r1 = &pb[2].x;
            uint32_t hh[8], ll[8];
#pragma unroll
            for (int j = 0; j < 8; j++)
                split_bf2(r0[j], r1[j], hh[j], ll[j]);
            *(uint4*)&sBh[bkp * GBP + bn0]     = *(uint4*)&hh[0];
            *(uint4*)&sBh[bkp * GBP + bn0 + 4] = *(uint4*)&hh[4];
            *(uint4*)&sBl[bkp * GBP + bn0]     = *(uint4*)&ll[0];
            *(uint4*)&sBl[bkp * GBP + bn0 + 4] = *(uint4*)&ll[4];
        }
        __syncthreads();

        if (kb < DIMC / 32 - 1) {
            int k0 = (kb + 1) * 32;
#pragma unroll
            for (int i = 0; i < 4; i++) {
                int flat = i * 1024 + tid * 4;
                pa[i] = *(const float4*)(A + (bm + (flat >> 5)) * DIMC + k0 + (flat & 31));
            }
            pb[0] = *(const float4*)(W + (k0 + 2 * bkp) * DIMC + bn + bn0);
            pb[1] = *(const float4*)(W + (k0 + 2 * bkp) * DIMC + bn + bn0 + 4);
            pb[2] = *(const float4*)(W + (k0 + 2 * bkp + 1) * DIMC + bn + bn0);
            pb[3] = *(const float4*)(W + (k0 + 2 * bkp + 1) * DIMC + bn + bn0 + 4);
        }

#pragma unroll
        for (int ks = 0; ks < 2; ks++) {
            const int kp0 = ks * 8;
            uint32_t ah[4][4], al[4][4];
#pragma unroll
            for (int mt = 0; mt < 4; mt++) {
                int r = wm * 64 + mt * 16 + gid;
                ah[mt][0] = sAh[r * GAP + kp0 + tg];
                ah[mt][1] = sAh[(r + 8) * GAP + kp0 + tg];
                ah[mt][2] = sAh[r * GAP + kp0 + 4 + tg];
                ah[mt][3] = sAh[(r + 8) * GAP + kp0 + 4 + tg];
                al[mt][0] = sAl[r * GAP + kp0 + tg];
                al[mt][1] = sAl[(r + 8) * GAP + kp0 + tg];
                al[mt][2] = sAl[r * GAP + kp0 + 4 + tg];
                al[mt][3] = sAl[(r + 8) * GAP + kp0 + 4 + tg];
            }
#pragma unroll
            for (int nt = 0; nt < 4; nt++) {
                int c = wn * 32 + nt * 8 + gid;
                uint32_t bh0 = sBh[(kp0 + tg) * GBP + c];
                uint32_t bh1 = sBh[(kp0 + 4 + tg) * GBP + c];
                uint32_t bl0 = sBl[(kp0 + tg) * GBP + c];
                uint32_t bl1 = sBl[(kp0 + 4 + tg) * GBP + c];
#pragma unroll
                for (int mt = 0; mt < 4; mt++)
                    mma3(acc[mt][nt], ah[mt], al[mt], bh0, bh1, bl0, bl1);
            }
        }
        __syncthreads();
    }
}

// ---------------------------------------------------------------------------
// QKV projection: C = X @ W scattered into [B,H,N,DH]. which: 0=q,1=k,2=v.
// ---------------------------------------------------------------------------
__global__ __launch_bounds__(256) void mma_gemm_qkv(
    const float* __restrict__ A, const float* __restrict__ W, int which)
{
    __shared__ __align__(16) uint32_t sAh[128 * GAP], sAl[128 * GAP];
    __shared__ __align__(16) uint32_t sBh[16 * GBP], sBl[16 * GBP];
    float* C = (which == 0) ? g_q : (which == 1) ? g_k : g_v;

    const int bm = blockIdx.x * 128;
    const int bn = blockIdx.y * 128;
    float acc[4][4][4];
#pragma unroll
    for (int mt = 0; mt < 4; mt++)
#pragma unroll
        for (int nt = 0; nt < 4; nt++)
#pragma unroll
            for (int c = 0; c < 4; c++) acc[mt][nt][c] = 0.f;

    gemm_mainloop(A, W, bm, bn, sAh, sAl, sBh, sBl, acc);

    const int lane = threadIdx.x & 31;
    const int warp = threadIdx.x >> 5;
    const int gid = lane >> 2, tg = lane & 3;
    const int wm = warp >> 2, wn = warp & 3;

#pragma unroll
    for (int mt = 0; mt < 4; mt++) {
        int row = bm + wm * 64 + mt * 16 + gid;
#pragma unroll
        for (int nt = 0; nt < 4; nt++) {
            int col = bn + wn * 32 + nt * 8 + 2 * tg;
            int h = col >> 6, d = col & 63;
#pragma unroll
            for (int half = 0; half < 2; half++) {
                int r = row + half * 8;
                int b = r >> 11, n = r & 2047;
                float2 v = make_float2(acc[mt][nt][2 * half], acc[mt][nt][2 * half + 1]);
                *(float2*)&C[(((size_t)(b * HEADS + h) * NSEQ) + n) * DHEAD + d] = v;
            }
        }
    }
}

// ---------------------------------------------------------------------------
// Wo projection: g_proj = g_attn @ Wo + bo
// ---------------------------------------------------------------------------
__global__ __launch_bounds__(256) void mma_gemm_wo(
    const float* __restrict__ W, const float* __restrict__ bo)
{
    __shared__ __align__(16) uint32_t sAh[128 * GAP], sAl[128 * GAP];
    __shared__ __align__(16) uint32_t sBh[16 * GBP], sBl[16 * GBP];

    const int bm = blockIdx.x * 128;
    const int bn = blockIdx.y * 128;
    float acc[4][4][4];
#pragma unroll
    for (int mt = 0; mt < 4; mt++)
#pragma unroll
        for (int nt = 0; nt < 4; nt++)
#pragma unroll
            for (int c = 0; c < 4; c++) acc[mt][nt][c] = 0.f;

    gemm_mainloop(g_attn, W, bm, bn, sAh, sAl, sBh, sBl, acc);

    const int lane = threadIdx.x & 31;
    const int warp = threadIdx.x >> 5;
    const int gid = lane >> 2, tg = lane & 3;
    const int wm = warp >> 2, wn = warp & 3;

#pragma unroll
    for (int mt = 0; mt < 4; mt++) {
        int row = bm + wm * 64 + mt * 16 + gid;
#pragma unroll
        for (int nt = 0; nt < 4; nt++) {
            int col = bn + wn * 32 + nt * 8 + 2 * tg;
            float b0 = bo[col], b1 = bo[col + 1];
#pragma unroll
            for (int half = 0; half < 2; half++) {
                int r = row + half * 8;
                float2 v = make_float2(acc[mt][nt][2 * half] + b0,
                                       acc[mt][nt][2 * half + 1] + b1);
                *(float2*)&g_proj[(size_t)r * DIMC + col] = v;
            }
        }
    }
}

// ---------------------------------------------------------------------------
// Flash attention v3. Grid: (N/128, B*H), 256 threads (8 warps).
// Warp owns 16 q rows (one m16 tile). KV tiles of 64. P stays in registers
// (S C-fragment == PV A-fragment). Q fragments hoisted to registers.
// smem: sQ hi/lo [128][36], sK hi/lo [64][36], sV hi/lo [32][72]  = 72 KB.
// ---------------------------------------------------------------------------
#define AQP 36
#define AKP 36
#define AVP 72
#define QW  (128 * AQP)
#define KW  (64 * AKP)
#define VW  (32 * AVP)
#define ATTN_SMEM ((2 * (QW + KW + VW)) * 4)

__global__ __launch_bounds__(256, 2) void attn_mma()
{
    extern __shared__ __align__(16) uint32_t smw[];
    uint32_t* sQh = smw;
    uint32_t* sQl = sQh + QW;
    uint32_t* sKh = sQl + QW;
    uint32_t* sKl = sKh + KW;
    uint32_t* sVh = sKl + KW;
    uint32_t* sVl = sVh + VW;

    const int tid = threadIdx.x;
    const int w = tid >> 5;
    const int lane = tid & 31;
    const int gid = lane >> 2, tg = lane & 3;
    const int qt = blockIdx.x;
    const int bh = blockIdx.y;

    const float* Qg = g_q + (size_t)bh * NSEQ * DHEAD + qt * 128 * DHEAD;
    const float* Kg = g_k + (size_t)bh * NSEQ * DHEAD;
    const float* Vg = g_v + (size_t)bh * NSEQ * DHEAD;

    // ---- load Q (scaled) into smem pairs ----
#pragma unroll
    for (int i = 0; i < 8; i++) {
        int flat = i * 1024 + tid * 4;
        int row = flat >> 6, d = flat & 63, kp = d >> 1;
        float4 v = *(const float4*)(Qg + row * DHEAD + d);
        v.x *= 0.125f; v.y *= 0.125f; v.z *= 0.125f; v.w *= 0.125f;
        uint32_t h0, l0, h1, l1;
        split_bf2(v.x, v.y, h0, l0);
        split_bf2(v.z, v.w, h1, l1);
        uint2 uh; uh.x = h0; uh.y = h1;
        uint2 ul; ul.x = l0; ul.y = l1;
        *(uint2*)&sQh[row * AQP + kp] = uh;
        *(uint2*)&sQl[row * AQP + kp] = ul;
    }
    __syncthreads();

    // ---- hoist Q fragments for this warp's 16 rows ----
    uint32_t qh[4][4], ql[4][4];
#pragma unroll
    for (int ks = 0; ks < 4; ks++) {
        const int kp0 = ks * 8;
        const int r = w * 16 + gid;
        qh[ks][0] = sQh[r * AQP + kp0 + tg];
        qh[ks][1] = sQh[(r + 8) * AQP + kp0 + tg];
        qh[ks][2] = sQh[r * AQP + kp0 + 4 + tg];
        qh[ks][3] = sQh[(r + 8) * AQP + kp0 + 4 + tg];
        ql[ks][0] = sQl[r * AQP + kp0 + tg];
        ql[ks][1] = sQl[(r + 8) * AQP + kp0 + tg];
        ql[ks][2] = sQl[r * AQP + kp0 + 4 + tg];
        ql[ks][3] = sQl[(r + 8) * AQP + kp0 + 4 + tg];
    }

    float m_[2], l_[2], o[8][4];
#pragma unroll
    for (int h = 0; h < 2; h++) { m_[h] = -1e30f; l_[h] = 0.f; }
#pragma unroll
    for (int nt = 0; nt < 8; nt++)
#pragma unroll
        for (int c = 0; c < 4; c++) o[nt][c] = 0.f;

    for (int kt = 0; kt < NSEQ / 64; kt++) {
        __syncthreads();   // previous iteration done reading sK/sV
        // ---- K tile: pairs along d ----
#pragma unroll
        for (int i = 0; i < 4; i++) {
            int flat = i * 1024 + tid * 4;
            int kv = flat >> 6, d = flat & 63, kp = d >> 1;
            float4 v = *(const float4*)(Kg + (kt * 64 + kv) * DHEAD + d);
            uint32_t h0, l0, h1, l1;
            split_bf2(v.x, v.y, h0, l0);
            split_bf2(v.z, v.w, h1, l1);
            uint2 uh; uh.x = h0; uh.y = h1;
            uint2 ul; ul.x = l0; ul.y = l1;
            *(uint2*)&sKh[kv * AKP + kp] = uh;
            *(uint2*)&sKl[kv * AKP + kp] = ul;
        }
        // ---- V tile: pairs along kv (cross-row) ----
#pragma unroll
        for (int i = 0; i < 2; i++) {
            int task = i * 256 + tid;
            int kvp = task >> 4, d0 = (task & 15) * 4;
            float4 v0 = *(const float4*)(Vg + (kt * 64 + 2 * kvp) * DHEAD + d0);
            float4 v1 = *(const float4*)(Vg + (kt * 64 + 2 * kvp + 1) * DHEAD + d0);
            uint32_t hh[4], ll[4];
            split_bf2(v0.x, v1.x, hh[0], ll[0]);
            split_bf2(v0.y, v1.y, hh[1], ll[1]);
            split_bf2(v0.z, v1.z, hh[2], ll[2]);
            split_bf2(v0.w, v1.w, hh[3], ll[3]);
            *(uint4*)&sVh[kvp * AVP + d0] = *(uint4*)&hh[0];
            *(uint4*)&sVl[kvp * AVP + d0] = *(uint4*)&ll[0];
        }
        __syncthreads();

        // ---- S = (Q/8) @ K^T  (16 x 64) ----
        float s[8][4];
#pragma unroll
        for (int nt = 0; nt < 8; nt++)
#pragma unroll
            for (int c = 0; c < 4; c++) s[nt][c] = 0.f;

#pragma unroll
        for (int ks = 0; ks < 4; ks++) {
            const int kp0 = ks * 8;
#pragma unroll
            for (int nt = 0; nt < 8; nt++) {
                int c = nt * 8 + gid;
                uint32_t bh0 = sKh[c * AKP + kp0 + tg];
                uint32_t bh1 = sKh[c * AKP + kp0 + 4 + tg];
                uint32_t bl0 = sKl[c * AKP + kp0 + tg];
                uint32_t bl1 = sKl[c * AKP + kp0 + 4 + tg];
                mma3(s[nt], qh[ks], ql[ks], bh0, bh1, bl0, bl1);
            }
        }

        // ---- online softmax (rows gid + 8h), p stays in s ----
#pragma unroll
        for (int h = 0; h < 2; h++) {
            float mx = -1e30f;
#pragma unroll
            for (int nt = 0; nt < 8; nt++)
                mx = fmaxf(mx, fmaxf(s[nt][2 * h], s[nt][2 * h + 1]));
            mx = fmaxf(mx, __shfl_xor_sync(0xffffffffu, mx, 1));
            mx = fmaxf(mx, __shfl_xor_sync(0xffffffffu, mx, 2));
            float mnew = fmaxf(m_[h], mx);
            float corr = __expf(m_[h] - mnew);
            m_[h] = mnew;
            float rs = 0.f;
#pragma unroll
            for (int nt = 0; nt < 8; nt++) {
                float p0 = __expf(s[nt][2 * h] - mnew);
                float p1 = __expf(s[nt][2 * h + 1] - mnew);
                s[nt][2 * h] = p0;
                s[nt][2 * h + 1] = p1;
                rs += p0 + p1;
            }
            rs += __shfl_xor_sync(0xffffffffu, rs, 1);
            rs += __shfl_xor_sync(0xffffffffu, rs, 2);
            l_[h] = l_[h] * corr + rs;
#pragma unroll
            for (int nt = 0; nt < 8; nt++) {
                o[nt][2 * h] *= corr;
                o[nt][2 * h + 1] *= corr;
            }
        }

        // ---- O += P @ V : P fragments built directly from s ----
#pragma unroll
        for (int ks = 0; ks < 4; ks++) {
            uint32_t pah[4], pal[4];
            split_bf2(s[2 * ks][0],     s[2 * ks][1],     pah[0], pal[0]);
            split_bf2(s[2 * ks][2],     s[2 * ks][3],     pah[1], pal[1]);
            split_bf2(s[2 * ks + 1][0], s[2 * ks + 1][1], pah[2], pal[2]);
            split_bf2(s[2 * ks + 1][2], s[2 * ks + 1][3], pah[3], pal[3]);
            const int kp0 = ks * 8;
#pragma unroll
            for (int nt = 0; nt < 8; nt++) {
                int d = nt * 8 + gid;
                uint32_t bh0 = sVh[(kp0 + tg) * AVP + d];
                uint32_t bh1 = sVh[(kp0 + 4 + tg) * AVP + d];
                uint32_t bl0 = sVl[(kp0 + tg) * AVP + d];
                uint32_t bl1 = sVl[(kp0 + 4 + tg) * AVP + d];
                mma3(o[nt], pah, pal, bh0, bh1, bl0, bl1);
            }
        }
    }

    // ---- epilogue: normalize, write [B,N,H*DH] ----
    const int b = bh >> 4;
    const int hh = bh & 15;
#pragma unroll
    for (int h = 0; h < 2; h++) {
        float inv = 1.0f / l_[h];
        int n = qt * 128 + w * 16 + gid + h * 8;
#pragma unroll
        for (int nt = 0; nt < 8; nt++) {
            int col = hh * DHEAD + nt * 8 + 2 * tg;
            float2 v = make_float2(o[nt][2 * h] * inv, o[nt][2 * h + 1] * inv);
            *(float2*)&g_attn[((size_t)b * NSEQ + n) * DIMC + col] = v;
        }
    }
}

// ---------------------------------------------------------------------------
// LayerNorm over last dim + residual. One block per row.
// ---------------------------------------------------------------------------
__global__ __launch_bounds__(256) void ln_kernel(
    const float* __restrict__ query, const float* __restrict__ gamma,
    const float* __restrict__ beta, float* __restrict__ out)
{
    const int r = blockIdx.x;
    const float* x = g_proj + (size_t)r * DIMC;

    float v[4];
    float s = 0.f, ss = 0.f;
#pragma unroll
    for (int i = 0; i < 4; i++) {
        v[i] = x[threadIdx.x + 256 * i];
        s += v[i];
        ss += v[i] * v[i];
    }
#pragma unroll
    for (int ofs = 16; ofs > 0; ofs >>= 1) {
        s  += __shfl_xor_sync(0xffffffffu, s,  ofs);
        ss += __shfl_xor_sync(0xffffffffu, ss, ofs);
    }
    __shared__ float rs[8], rss[8];
    int w = threadIdx.x >> 5, lane = threadIdx.x & 31;
    if (lane == 0) { rs[w] = s; rss[w] = ss; }
    __syncthreads();
    if (threadIdx.x == 0) {
        float a = 0.f, b2 = 0.f;
#pragma unroll
        for (int i = 0; i < 8; i++) { a += rs[i]; b2 += rss[i]; }
        rs[0] = a; rss[0] = b2;
    }
    __syncthreads();
    const float mean = rs[0] * (1.0f / DIMC);
    const float var  = rss[0] * (1.0f / DIMC) - mean * mean;
    const float inv  = rsqrtf(var + 1e-5f);

#pragma unroll
    for (int i = 0; i < 4; i++) {
        int c = threadIdx.x + 256 * i;
        size_t idx = (size_t)r * DIMC + c;
        out[idx] = (v[i] - mean) * inv * gamma[c] + beta[c] + query[idx];
    }
}

// ---------------------------------------------------------------------------
extern "C" void kernel_launch(void* const* d_in, const int* in_sizes, int n_in,
                              void* d_out, int out_size)
{
    const float* query = (const float*)d_in[0];
    const float* key_  = (const float*)d_in[1];
    const float* value = (const float*)d_in[2];
    const float* Wq    = (const float*)d_in[3];
    const float* Wk    = (const float*)d_in[4];
    const float* Wv    = (const float*)d_in[5];
    const float* Wo    = (const float*)d_in[6];
    const float* bo    = (const float*)d_in[7];
    const float* gamma = (const float*)d_in[8];
    const float* beta  = (const float*)d_in[9];
    float* out = (float*)d_out;

    cudaFuncSetAttribute(attn_mma,
                         cudaFuncAttributeMaxDynamicSharedMemorySize, ATTN_SMEM);

    dim3 ggrid(MTOT / 128, DIMC / 128);
    // 1) QKV projections -> [B,H,N,DH]
    mma_gemm_qkv<<<ggrid, 256>>>(query, Wq, 0);
    mma_gemm_qkv<<<ggrid, 256>>>(key_,  Wk, 1);
    mma_gemm_qkv<<<ggrid, 256>>>(value, Wv, 2);
    // 2) Attention -> [B,N,H*DH]
    attn_mma<<<dim3(NSEQ / 128, BC * HEADS), 256, ATTN_SMEM>>>();
    // 3) Wo projection + bias
    mma_gemm_wo<<<ggrid, 256>>>(Wo, bo);
    // 4) LayerNorm + residual
    ln_kernel<<<MTOT, 256>>>(query, gamma, beta, out);
}

// round 10
// speedup vs baseline: 2.6953x; 1.0002x over previous
#include <cuda_runtime.h>
#include <cstdint>

// ---------------------------------------------------------------------------
// MultiHeadAttention: out = LN( softmax(QK^T/sqrt(d)) V @ Wo + bo ) + query
// B=4, N=2048, DIM=1024, HEADS=16, DH=64
// Round-8: bf16-split mma; attention restructured: 8 warps, P-in-registers,
// Q fragments hoisted, 72KB smem -> 2 CTAs/SM.
// ---------------------------------------------------------------------------

#define BC    4
#define NSEQ  2048
#define DIMC  1024
#define HEADS 16
#define DHEAD 64
#define MTOT  (BC * NSEQ)   // 8192

__device__ float g_q[MTOT * DIMC];     // [B,H,N,DH]
__device__ float g_k[MTOT * DIMC];     // [B,H,N,DH]
__device__ float g_v[MTOT * DIMC];     // [B,H,N,DH]
__device__ float g_attn[MTOT * DIMC];  // [B,N,H*DH]
__device__ float g_proj[MTOT * DIMC];  // attn @ Wo + bo

// ---------------------------------------------------------------------------
// bf16 split helpers: x = hi + lo, both bf16; packed as bf16x2 (low = elem k)
// ---------------------------------------------------------------------------
__device__ __forceinline__ uint32_t pack_bf2(float x0, float x1)
{
    uint32_t p;
    asm("cvt.rn.satfinite.bf16x2.f32 %0, %1, %2;" : "=r"(p) : "f"(x1), "f"(x0));
    return p;
}

__device__ __forceinline__ void split_bf2(float x0, float x1,
                                          uint32_t& hi, uint32_t& lo)
{
    uint32_t h = pack_bf2(x0, x1);
    float h0 = __uint_as_float(h << 16);
    float h1 = __uint_as_float(h & 0xffff0000u);
    lo = pack_bf2(x0 - h0, x1 - h1);
    hi = h;
}

__device__ __forceinline__ void mma16(float* d,
                                      uint32_t a0, uint32_t a1, uint32_t a2, uint32_t a3,
                                      uint32_t b0, uint32_t b1)
{
    asm volatile(
        "mma.sync.aligned.m16n8k16.row.col.f32.bf16.bf16.f32 "
        "{%0,%1,%2,%3}, {%4,%5,%6,%7}, {%8,%9}, {%0,%1,%2,%3};\n"
        : "+f"(d[0]), "+f"(d[1]), "+f"(d[2]), "+f"(d[3])
        : "r"(a0), "r"(a1), "r"(a2), "r"(a3), "r"(b0), "r"(b1));
}

// 3-term: D += Ah*Bl + Al*Bh + Ah*Bh  (low-order terms first)
__device__ __forceinline__ void mma3(float* d,
                                     const uint32_t* ah, const uint32_t* al,
                                     uint32_t bh0, uint32_t bh1,
                                     uint32_t bl0, uint32_t bl1)
{
    mma16(d, ah[0], ah[1], ah[2], ah[3], bl0, bl1);
    mma16(d, al[0], al[1], al[2], al[3], bh0, bh1);
    mma16(d, ah[0], ah[1], ah[2], ah[3], bh0, bh1);
}

// ---------------------------------------------------------------------------
// GEMM: 128x128 block, BK=32, 256 threads (8 warps 2x4), warp tile 64x32.
// A smem: row-major pairs [128 rows][20 kp-words]; B smem: [16 kp][136 n].
// ---------------------------------------------------------------------------
#define GAP 20
#define GBP 136

__device__ __forceinline__ void gemm_mainloop(
    const float* __restrict__ A, const float* __restrict__ W,
    int bm, int bn,
    uint32_t* sAh, uint32_t* sAl, uint32_t* sBh, uint32_t* sBl,
    float acc[4][4][4])
{
    const int tid = threadIdx.x;
    const int lane = tid & 31;
    const int warp = tid >> 5;
    const int gid = lane >> 2;
    const int tg = lane & 3;
    const int wm = warp >> 2;   // 0..1
    const int wn = warp & 3;    // 0..3

    const int bkp = tid >> 4;           // 0..15
    const int bn0 = (tid & 15) * 8;     // 0..120

    float4 pa[4], pb[4];
#pragma unroll
    for (int i = 0; i < 4; i++) {
        int flat = i * 1024 + tid * 4;
        pa[i] = *(const float4*)(A + (bm + (flat >> 5)) * DIMC + (flat & 31));
    }
    pb[0] = *(const float4*)(W + (2 * bkp) * DIMC + bn + bn0);
    pb[1] = *(const float4*)(W + (2 * bkp) * DIMC + bn + bn0 + 4);
    pb[2] = *(const float4*)(W + (2 * bkp + 1) * DIMC + bn + bn0);
    pb[3] = *(const float4*)(W + (2 * bkp + 1) * DIMC + bn + bn0 + 4);

    for (int kb = 0; kb < DIMC / 32; kb++) {
#pragma unroll
        for (int i = 0; i < 4; i++) {
            int flat = i * 1024 + tid * 4;
            int row = flat >> 5, kp = (flat & 31) >> 1;
            uint32_t h0, l0, h1, l1;
            split_bf2(pa[i].x, pa[i].y, h0, l0);
            split_bf2(pa[i].z, pa[i].w, h1, l1);
            uint2 uh; uh.x = h0; uh.y = h1;
            uint2 ul; ul.x = l0; ul.y = l1;
            *(uint2*)&sAh[row * GAP + kp] = uh;
            *(uint2*)&sAl[row * GAP + kp] = ul;
        }
        {
            const float* r0 = &pb[0].x;
            const float* r1 = &pb[2].x;
            uint32_t hh[8], ll[8];
#pragma unroll
            for (int j = 0; j < 8; j++)
                split_bf2(r0[j], r1[j], hh[j], ll[j]);
            *(uint4*)&sBh[bkp * GBP + bn0]     = *(uint4*)&hh[0];
            *(uint4*)&sBh[bkp * GBP + bn0 + 4] = *(uint4*)&hh[4];
            *(uint4*)&sBl[bkp * GBP + bn0]     = *(uint4*)&ll[0];
            *(uint4*)&sBl[bkp * GBP + bn0 + 4] = *(uint4*)&ll[4];
        }
        __syncthreads();

        if (kb < DIMC / 32 - 1) {
            int k0 = (kb + 1) * 32;
#pragma unroll
            for (int i = 0; i < 4; i++) {
                int flat = i * 1024 + tid * 4;
                pa[i] = *(const float4*)(A + (bm + (flat >> 5)) * DIMC + k0 + (flat & 31));
            }
            pb[0] = *(const float4*)(W + (k0 + 2 * bkp) * DIMC + bn + bn0);
            pb[1] = *(const float4*)(W + (k0 + 2 * bkp) * DIMC + bn + bn0 + 4);
            pb[2] = *(const float4*)(W + (k0 + 2 * bkp + 1) * DIMC + bn + bn0);
            pb[3] = *(const float4*)(W + (k0 + 2 * bkp + 1) * DIMC + bn + bn0 + 4);
        }

#pragma unroll
        for (int ks = 0; ks < 2; ks++) {
            const int kp0 = ks * 8;
            uint32_t ah[4][4], al[4][4];
#pragma unroll
            for (int mt = 0; mt < 4; mt++) {
                int r = wm * 64 + mt * 16 + gid;
                ah[mt][0] = sAh[r * GAP + kp0 + tg];
                ah[mt][1] = sAh[(r + 8) * GAP + kp0 + tg];
                ah[mt][2] = sAh[r * GAP + kp0 + 4 + tg];
                ah[mt][3] = sAh[(r + 8) * GAP + kp0 + 4 + tg];
                al[mt][0] = sAl[r * GAP + kp0 + tg];
                al[mt][1] = sAl[(r + 8) * GAP + kp0 + tg];
                al[mt][2] = sAl[r * GAP + kp0 + 4 + tg];
                al[mt][3] = sAl[(r + 8) * GAP + kp0 + 4 + tg];
            }
#pragma unroll
            for (int nt = 0; nt < 4; nt++) {
                int c = wn * 32 + nt * 8 + gid;
                uint32_t bh0 = sBh[(kp0 + tg) * GBP + c];
                uint32_t bh1 = sBh[(kp0 + 4 + tg) * GBP + c];
                uint32_t bl0 = sBl[(kp0 + tg) * GBP + c];
                uint32_t bl1 = sBl[(kp0 + 4 + tg) * GBP + c];
#pragma unroll
                for (int mt = 0; mt < 4; mt++)
                    mma3(acc[mt][nt], ah[mt], al[mt], bh0, bh1, bl0, bl1);
            }
        }
        __syncthreads();
    }
}

// ---------------------------------------------------------------------------
// QKV projection: C = X @ W scattered into [B,H,N,DH]. which: 0=q,1=k,2=v.
// ---------------------------------------------------------------------------
__global__ __launch_bounds__(256) void mma_gemm_qkv(
    const float* __restrict__ A, const float* __restrict__ W, int which)
{
    __shared__ __align__(16) uint32_t sAh[128 * GAP], sAl[128 * GAP];
    __shared__ __align__(16) uint32_t sBh[16 * GBP], sBl[16 * GBP];
    float* C = (which == 0) ? g_q : (which == 1) ? g_k : g_v;

    const int bm = blockIdx.x * 128;
    const int bn = blockIdx.y * 128;
    float acc[4][4][4];
#pragma unroll
    for (int mt = 0; mt < 4; mt++)
#pragma unroll
        for (int nt = 0; nt < 4; nt++)
#pragma unroll
            for (int c = 0; c < 4; c++) acc[mt][nt][c] = 0.f;

    gemm_mainloop(A, W, bm, bn, sAh, sAl, sBh, sBl, acc);

    const int lane = threadIdx.x & 31;
    const int warp = threadIdx.x >> 5;
    const int gid = lane >> 2, tg = lane & 3;
    const int wm = warp >> 2, wn = warp & 3;

#pragma unroll
    for (int mt = 0; mt < 4; mt++) {
        int row = bm + wm * 64 + mt * 16 + gid;
#pragma unroll
        for (int nt = 0; nt < 4; nt++) {
            int col = bn + wn * 32 + nt * 8 + 2 * tg;
            int h = col >> 6, d = col & 63;
#pragma unroll
            for (int half = 0; half < 2; half++) {
                int r = row + half * 8;
                int b = r >> 11, n = r & 2047;
                float2 v = make_float2(acc[mt][nt][2 * half], acc[mt][nt][2 * half + 1]);
                *(float2*)&C[(((size_t)(b * HEADS + h) * NSEQ) + n) * DHEAD + d] = v;
            }
        }
    }
}

// ---------------------------------------------------------------------------
// Wo projection: g_proj = g_attn @ Wo + bo
// ---------------------------------------------------------------------------
__global__ __launch_bounds__(256) void mma_gemm_wo(
    const float* __restrict__ W, const float* __restrict__ bo)
{
    __shared__ __align__(16) uint32_t sAh[128 * GAP], sAl[128 * GAP];
    __shared__ __align__(16) uint32_t sBh[16 * GBP], sBl[16 * GBP];

    const int bm = blockIdx.x * 128;
    const int bn = blockIdx.y * 128;
    float acc[4][4][4];
#pragma unroll
    for (int mt = 0; mt < 4; mt++)
#pragma unroll
        for (int nt = 0; nt < 4; nt++)
#pragma unroll
            for (int c = 0; c < 4; c++) acc[mt][nt][c] = 0.f;

    gemm_mainloop(g_attn, W, bm, bn, sAh, sAl, sBh, sBl, acc);

    const int lane = threadIdx.x & 31;
    const int warp = threadIdx.x >> 5;
    const int gid = lane >> 2, tg = lane & 3;
    const int wm = warp >> 2, wn = warp & 3;

#pragma unroll
    for (int mt = 0; mt < 4; mt++) {
        int row = bm + wm * 64 + mt * 16 + gid;
#pragma unroll
        for (int nt = 0; nt < 4; nt++) {
            int col = bn + wn * 32 + nt * 8 + 2 * tg;
            float b0 = bo[col], b1 = bo[col + 1];
#pragma unroll
            for (int half = 0; half < 2; half++) {
                int r = row + half * 8;
                float2 v = make_float2(acc[mt][nt][2 * half] + b0,
                                       acc[mt][nt][2 * half + 1] + b1);
                *(float2*)&g_proj[(size_t)r * DIMC + col] = v;
            }
        }
    }
}

// ---------------------------------------------------------------------------
// Flash attention v3. Grid: (N/128, B*H), 256 threads (8 warps).
// Warp owns 16 q rows (one m16 tile). KV tiles of 64. P stays in registers
// (S C-fragment == PV A-fragment). Q fragments hoisted to registers.
// smem: sQ hi/lo [128][36], sK hi/lo [64][36], sV hi/lo [32][72]  = 72 KB.
// ---------------------------------------------------------------------------
#define AQP 36
#define AKP 36
#define AVP 72
#define QW  (128 * AQP)
#define KW  (64 * AKP)
#define VW  (32 * AVP)
#define ATTN_SMEM ((2 * (QW + KW + VW)) * 4)

__global__ __launch_bounds__(256, 2) void attn_mma()
{
    extern __shared__ __align__(16) uint32_t smw[];
    uint32_t* sQh = smw;
    uint32_t* sQl = sQh + QW;
    uint32_t* sKh = sQl + QW;
    uint32_t* sKl = sKh + KW;
    uint32_t* sVh = sKl + KW;
    uint32_t* sVl = sVh + VW;

    const int tid = threadIdx.x;
    const int w = tid >> 5;
    const int lane = tid & 31;
    const int gid = lane >> 2, tg = lane & 3;
    const int qt = blockIdx.x;
    const int bh = blockIdx.y;

    const float* Qg = g_q + (size_t)bh * NSEQ * DHEAD + qt * 128 * DHEAD;
    const float* Kg = g_k + (size_t)bh * NSEQ * DHEAD;
    const float* Vg = g_v + (size_t)bh * NSEQ * DHEAD;

    // ---- load Q (scaled) into smem pairs ----
#pragma unroll
    for (int i = 0; i < 8; i++) {
        int flat = i * 1024 + tid * 4;
        int row = flat >> 6, d = flat & 63, kp = d >> 1;
        float4 v = *(const float4*)(Qg + row * DHEAD + d);
        v.x *= 0.125f; v.y *= 0.125f; v.z *= 0.125f; v.w *= 0.125f;
        uint32_t h0, l0, h1, l1;
        split_bf2(v.x, v.y, h0, l0);
        split_bf2(v.z, v.w, h1, l1);
        uint2 uh; uh.x = h0; uh.y = h1;
        uint2 ul; ul.x = l0; ul.y = l1;
        *(uint2*)&sQh[row * AQP + kp] = uh;
        *(uint2*)&sQl[row * AQP + kp] = ul;
    }
    __syncthreads();

    // ---- hoist Q fragments for this warp's 16 rows ----
    uint32_t qh[4][4], ql[4][4];
#pragma unroll
    for (int ks = 0; ks < 4; ks++) {
        const int kp0 = ks * 8;
        const int r = w * 16 + gid;
        qh[ks][0] = sQh[r * AQP + kp0 + tg];
        qh[ks][1] = sQh[(r + 8) * AQP + kp0 + tg];
        qh[ks][2] = sQh[r * AQP + kp0 + 4 + tg];
        qh[ks][3] = sQh[(r + 8) * AQP + kp0 + 4 + tg];
        ql[ks][0] = sQl[r * AQP + kp0 + tg];
        ql[ks][1] = sQl[(r + 8) * AQP + kp0 + tg];
        ql[ks][2] = sQl[r * AQP + kp0 + 4 + tg];
        ql[ks][3] = sQl[(r + 8) * AQP + kp0 + 4 + tg];
    }

    float m_[2], l_[2], o[8][4];
#pragma unroll
    for (int h = 0; h < 2; h++) { m_[h] = -1e30f; l_[h] = 0.f; }
#pragma unroll
    for (int nt = 0; nt < 8; nt++)
#pragma unroll
        for (int c = 0; c < 4; c++) o[nt][c] = 0.f;

    for (int kt = 0; kt < NSEQ / 64; kt++) {
        __syncthreads();   // previous iteration done reading sK/sV
        // ---- K tile: pairs along d ----
#pragma unroll
        for (int i = 0; i < 4; i++) {
            int flat = i * 1024 + tid * 4;
            int kv = flat >> 6, d = flat & 63, kp = d >> 1;
            float4 v = *(const float4*)(Kg + (kt * 64 + kv) * DHEAD + d);
            uint32_t h0, l0, h1, l1;
            split_bf2(v.x, v.y, h0, l0);
            split_bf2(v.z, v.w, h1, l1);
            uint2 uh; uh.x = h0; uh.y = h1;
            uint2 ul; ul.x = l0; ul.y = l1;
            *(uint2*)&sKh[kv * AKP + kp] = uh;
            *(uint2*)&sKl[kv * AKP + kp] = ul;
        }
        // ---- V tile: pairs along kv (cross-row) ----
#pragma unroll
        for (int i = 0; i < 2; i++) {
            int task = i * 256 + tid;
            int kvp = task >> 4, d0 = (task & 15) * 4;
            float4 v0 = *(const float4*)(Vg + (kt * 64 + 2 * kvp) * DHEAD + d0);
            float4 v1 = *(const float4*)(Vg + (kt * 64 + 2 * kvp + 1) * DHEAD + d0);
            uint32_t hh[4], ll[4];
            split_bf2(v0.x, v1.x, hh[0], ll[0]);
            split_bf2(v0.y, v1.y, hh[1], ll[1]);
            split_bf2(v0.z, v1.z, hh[2], ll[2]);
            split_bf2(v0.w, v1.w, hh[3], ll[3]);
            *(uint4*)&sVh[kvp * AVP + d0] = *(uint4*)&hh[0];
            *(uint4*)&sVl[kvp * AVP + d0] = *(uint4*)&ll[0];
        }
        __syncthreads();

        // ---- S = (Q/8) @ K^T  (16 x 64) ----
        float s[8][4];
#pragma unroll
        for (int nt = 0; nt < 8; nt++)
#pragma unroll
            for (int c = 0; c < 4; c++) s[nt][c] = 0.f;

#pragma unroll
        for (int ks = 0; ks < 4; ks++) {
            const int kp0 = ks * 8;
#pragma unroll
            for (int nt = 0; nt < 8; nt++) {
                int c = nt * 8 + gid;
                uint32_t bh0 = sKh[c * AKP + kp0 + tg];
                uint32_t bh1 = sKh[c * AKP + kp0 + 4 + tg];
                uint32_t bl0 = sKl[c * AKP + kp0 + tg];
                uint32_t bl1 = sKl[c * AKP + kp0 + 4 + tg];
                mma3(s[nt], qh[ks], ql[ks], bh0, bh1, bl0, bl1);
            }
        }

        // ---- online softmax (rows gid + 8h), p stays in s ----
#pragma unroll
        for (int h = 0; h < 2; h++) {
            float mx = -1e30f;
#pragma unroll
            for (int nt = 0; nt < 8; nt++)
                mx = fmaxf(mx, fmaxf(s[nt][2 * h], s[nt][2 * h + 1]));
            mx = fmaxf(mx, __shfl_xor_sync(0xffffffffu, mx, 1));
            mx = fmaxf(mx, __shfl_xor_sync(0xffffffffu, mx, 2));
            float mnew = fmaxf(m_[h], mx);
            float corr = __expf(m_[h] - mnew);
            m_[h] = mnew;
            float rs = 0.f;
#pragma unroll
            for (int nt = 0; nt < 8; nt++) {
                float p0 = __expf(s[nt][2 * h] - mnew);
                float p1 = __expf(s[nt][2 * h + 1] - mnew);
                s[nt][2 * h] = p0;
                s[nt][2 * h + 1] = p1;
                rs += p0 + p1;
            }
            rs += __shfl_xor_sync(0xffffffffu, rs, 1);
            rs += __shfl_xor_sync(0xffffffffu, rs, 2);
            l_[h] = l_[h] * corr + rs;
#pragma unroll
            for (int nt = 0; nt < 8; nt++) {
                o[nt][2 * h] *= corr;
                o[nt][2 * h + 1] *= corr;
            }
        }

        // ---- O += P @ V : P fragments built directly from s ----
#pragma unroll
        for (int ks = 0; ks < 4; ks++) {
            uint32_t pah[4], pal[4];
            split_bf2(s[2 * ks][0],     s[2 * ks][1],     pah[0], pal[0]);
            split_bf2(s[2 * ks][2],     s[2 * ks][3],     pah[1], pal[1]);
            split_bf2(s[2 * ks + 1][0], s[2 * ks + 1][1], pah[2], pal[2]);
            split_bf2(s[2 * ks + 1][2], s[2 * ks + 1][3], pah[3], pal[3]);
            const int kp0 = ks * 8;
#pragma unroll
            for (int nt = 0; nt < 8; nt++) {
                int d = nt * 8 + gid;
                uint32_t bh0 = sVh[(kp0 + tg) * AVP + d];
                uint32_t bh1 = sVh[(kp0 + 4 + tg) * AVP + d];
                uint32_t bl0 = sVl[(kp0 + tg) * AVP + d];
                uint32_t bl1 = sVl[(kp0 + 4 + tg) * AVP + d];
                mma3(o[nt], pah, pal, bh0, bh1, bl0, bl1);
            }
        }
    }

    // ---- epilogue: normalize, write [B,N,H*DH] ----
    const int b = bh >> 4;
    const int hh = bh & 15;
#pragma unroll
    for (int h = 0; h < 2; h++) {
        float inv = 1.0f / l_[h];
        int n = qt * 128 + w * 16 + gid + h * 8;
#pragma unroll
        for (int nt = 0; nt < 8; nt++) {
            int col = hh * DHEAD + nt * 8 + 2 * tg;
            float2 v = make_float2(o[nt][2 * h] * inv, o[nt][2 * h + 1] * inv);
            *(float2*)&g_attn[((size_t)b * NSEQ + n) * DIMC + col] = v;
        }
    }
}

// ---------------------------------------------------------------------------
// LayerNorm over last dim + residual. One block per row.
// ---------------------------------------------------------------------------
__global__ __launch_bounds__(256) void ln_kernel(
    const float* __restrict__ query, const float* __restrict__ gamma,
    const float* __restrict__ beta, float* __restrict__ out)
{
    const int r = blockIdx.x;
    const float* x = g_proj + (size_t)r * DIMC;

    float v[4];
    float s = 0.f, ss = 0.f;
#pragma unroll
    for (int i = 0; i < 4; i++) {
        v[i] = x[threadIdx.x + 256 * i];
        s += v[i];
        ss += v[i] * v[i];
    }
#pragma unroll
    for (int ofs = 16; ofs > 0; ofs >>= 1) {
        s  += __shfl_xor_sync(0xffffffffu, s,  ofs);
        ss += __shfl_xor_sync(0xffffffffu, ss, ofs);
    }
    __shared__ float rs[8], rss[8];
    int w = threadIdx.x >> 5, lane = threadIdx.x & 31;
    if (lane == 0) { rs[w] = s; rss[w] = ss; }
    __syncthreads();
    if (threadIdx.x == 0) {
        float a = 0.f, b2 = 0.f;
#pragma unroll
        for (int i = 0; i < 8; i++) { a += rs[i]; b2 += rss[i]; }
        rs[0] = a; rss[0] = b2;
    }
    __syncthreads();
    const float mean = rs[0] * (1.0f / DIMC);
    const float var  = rss[0] * (1.0f / DIMC) - mean * mean;
    const float inv  = rsqrtf(var + 1e-5f);

#pragma unroll
    for (int i = 0; i < 4; i++) {
        int c = threadIdx.x + 256 * i;
        size_t idx = (size_t)r * DIMC + c;
        out[idx] = (v[i] - mean) * inv * gamma[c] + beta[c] + query[idx];
    }
}

// ---------------------------------------------------------------------------
extern "C" void kernel_launch(void* const* d_in, const int* in_sizes, int n_in,
                              void* d_out, int out_size)
{
    const float* query = (const float*)d_in[0];
    const float* key_  = (const float*)d_in[1];
    const float* value = (const float*)d_in[2];
    const float* Wq    = (const float*)d_in[3];
    const float* Wk    = (const float*)d_in[4];
    const float* Wv    = (const float*)d_in[5];
    const float* Wo    = (const float*)d_in[6];
    const float* bo    = (const float*)d_in[7];
    const float* gamma = (const float*)d_in[8];
    const float* beta  = (const float*)d_in[9];
    float* out = (float*)d_out;

    cudaFuncSetAttribute(attn_mma,
                         cudaFuncAttributeMaxDynamicSharedMemorySize, ATTN_SMEM);

    dim3 ggrid(MTOT / 128, DIMC / 128);
    // 1) QKV projections -> [B,H,N,DH]
    mma_gemm_qkv<<<ggrid, 256>>>(query, Wq, 0);
    mma_gemm_qkv<<<ggrid, 256>>>(key_,  Wk, 1);
    mma_gemm_qkv<<<ggrid, 256>>>(value, Wv, 2);
    // 2) Attention -> [B,N,H*DH]
    attn_mma<<<dim3(NSEQ / 128, BC * HEADS), 256, ATTN_SMEM>>>();
    // 3) Wo projection + bias
    mma_gemm_wo<<<ggrid, 256>>>(Wo, bo);
    // 4) LayerNorm + residual
    ln_kernel<<<MTOT, 256>>>(query, gamma, beta, out);
}